// round 1
// baseline (speedup 1.0000x reference)
#include <cuda_runtime.h>
#include <math.h>
#include <stdint.h>

// ---------------- problem constants ----------------
#define G_  100        // B*S graphs
#define N_  2500       // nodes per graph
#define E_  7500       // edges per graph
#define TOT_NODES 250000
#define TOT_EDGES 750000
#define T_  52         // sequence length (S+2)
#define D_  32         // d_model

// ---------------- scratch (static, allocation-free) ----------------
// arena (floats): xw1 [0,32M) ; h1 [32M,64M) ; xw2 [64M,128M)
// h2 aliases [0,64M) (xw1 & h1 are dead by the time h2 is written)
#define XW1_OFF 0
#define H1_OFF  32000000
#define XW2_OFF 64000000
__device__ float g_arena[128000000];          // 512 MB
__device__ float g_dinv[TOT_NODES];
__device__ int   g_cnt[TOT_NODES];
__device__ int   g_off[G_*(N_+1)];
__device__ int   g_cur[TOT_NODES];
__device__ int   g_rows[TOT_EDGES];
__device__ float g_xseq[T_*2*D_];             // [t][b][d]
__device__ float g_qkv [T_*2*96];
__device__ float g_attn[T_*2*D_];

// ---------------- helpers ----------------
__device__ __forceinline__ float2 ffma2(float2 a, float2 b, float2 c) {
    union U { float2 f; unsigned long long u; } ua, ub, uc;
    ua.f = a; ub.f = b; uc.f = c;
    asm("fma.rn.f32x2 %0, %1, %2, %3;" : "=l"(uc.u) : "l"(ua.u), "l"(ub.u), "l"(uc.u));
    return uc.f;
}

__device__ __forceinline__ float warp_sum(float v) {
#pragma unroll
    for (int o = 16; o; o >>= 1) v += __shfl_xor_sync(0xffffffffu, v, o);
    return v;
}

__device__ __forceinline__ float leaky(float x) {
    return x >= 0.0f ? x : 0.15f * x;
}

// ---------------- GCN stage ----------------

__global__ void k_zero() {
    int i = blockIdx.x * 256 + threadIdx.x;
    if (i < TOT_NODES) g_cnt[i] = 0;
}

// embed (3 -> 64, relu) fused with xw1 = x @ W_g1 (64 -> 128), no bias.
// block: 128 threads (= out channel), 40 nodes per block. grid 6250.
__global__ void k_embed_xw1(const float* __restrict__ v, const float* __restrict__ W_emb,
                            const float* __restrict__ b_emb, const float* __restrict__ W_g1) {
    __shared__ __align__(16) float xs[64*40];   // transposed: xs[k*40 + m]
    __shared__ float ws[64*128];
    int n0 = blockIdx.x * 40;
    int t  = threadIdx.x;
    for (int idx = t; idx < 40*64; idx += 128) {
        int m = idx >> 6, c = idx & 63;
        const float* vp = v + (size_t)(n0 + m) * 3;
        float val = b_emb[c];
        val = fmaf(vp[0], W_emb[c],      val);
        val = fmaf(vp[1], W_emb[64 + c], val);
        val = fmaf(vp[2], W_emb[128 + c], val);
        xs[c*40 + m] = fmaxf(val, 0.0f);
    }
    for (int idx = t; idx < 64*128; idx += 128) ws[idx] = W_g1[idx];
    __syncthreads();

    float2 acc[20];
#pragma unroll
    for (int j = 0; j < 20; j++) acc[j] = make_float2(0.f, 0.f);
    for (int k = 0; k < 64; k++) {
        float w = ws[k*128 + t];
        float2 w2 = make_float2(w, w);
        const float4* ap = (const float4*)(xs + k*40);
#pragma unroll
        for (int j = 0; j < 10; j++) {
            float4 a = ap[j];
            acc[2*j]   = ffma2(make_float2(a.x, a.y), w2, acc[2*j]);
            acc[2*j+1] = ffma2(make_float2(a.z, a.w), w2, acc[2*j+1]);
        }
    }
    float* out = g_arena + XW1_OFF;
#pragma unroll
    for (int j = 0; j < 10; j++) {
        int m = 4*j;
        out[(size_t)(n0+m  )*128 + t] = acc[2*j].x;
        out[(size_t)(n0+m+1)*128 + t] = acc[2*j].y;
        out[(size_t)(n0+m+2)*128 + t] = acc[2*j+1].x;
        out[(size_t)(n0+m+3)*128 + t] = acc[2*j+1].y;
    }
}

__global__ void k_deg(const int* __restrict__ edge) {
    int e = blockIdx.x * 256 + threadIdx.x;
    if (e < TOT_EDGES) {
        int g = e / E_;
        int col = edge[2*e + 1];
        atomicAdd(&g_cnt[g*N_ + col], 1);
    }
}

__global__ void k_dinv() {
    int i = blockIdx.x * 256 + threadIdx.x;
    if (i < TOT_NODES) g_dinv[i] = rsqrtf((float)g_cnt[i] + 1.0f);
}

// per-graph exclusive scan of counts -> CSR offsets (+ cursor copy). grid G_, 256 thr.
__global__ void k_scan() {
    int g = blockIdx.x;
    int tid = threadIdx.x;
    __shared__ int sm[256];
    int base = tid * 10;
    int loc[10];
    int s = 0;
    if (base < N_) {
#pragma unroll
        for (int i = 0; i < 10; i++) { loc[i] = g_cnt[g*N_ + base + i]; s += loc[i]; }
    }
    sm[tid] = s;
    __syncthreads();
    for (int ofs = 1; ofs < 256; ofs <<= 1) {
        int vv = (tid >= ofs) ? sm[tid - ofs] : 0;
        __syncthreads();
        sm[tid] += vv;
        __syncthreads();
    }
    int excl = sm[tid] - s;
    if (base < N_) {
        int off = excl;
#pragma unroll
        for (int i = 0; i < 10; i++) {
            g_off[g*(N_+1) + base + i] = off;
            g_cur[g*N_ + base + i] = off;
            off += loc[i];
        }
    }
    if (tid == 255) g_off[g*(N_+1) + N_] = sm[255];
}

__global__ void k_fill(const int* __restrict__ edge) {
    int e = blockIdx.x * 256 + threadIdx.x;
    if (e < TOT_EDGES) {
        int g = e / E_;
        int row = edge[2*e];
        int col = edge[2*e + 1];
        int pos = atomicAdd(&g_cur[g*N_ + col], 1);
        g_rows[g*E_ + pos] = row;
    }
}

// gather + self-loop + bias + leaky, 128 channels. grid TOT_NODES, 128 thr.
__global__ void k_gather1(const float* __restrict__ b_g1) {
    int node = blockIdx.x;
    int g = node / N_;
    int ln = node - g * N_;
    int t = threadIdx.x;
    const float* xw1 = g_arena + XW1_OFF;
    float di = g_dinv[node];
    float acc = di * di * xw1[(size_t)node*128 + t];
    int o0 = g_off[g*(N_+1) + ln];
    int o1 = g_off[g*(N_+1) + ln + 1];
    const int* rows = g_rows + g*E_;
    const float* dv = g_dinv + g*N_;
    size_t gb = (size_t)g * N_ * 128;
    for (int e = o0; e < o1; e++) {
        int r = rows[e];
        acc = fmaf(di * dv[r], xw1[gb + (size_t)r*128 + t], acc);
    }
    acc += b_g1[t];
    g_arena[H1_OFF + (size_t)node*128 + t] = leaky(acc);
}

// xw2 = h1 @ W_g2 : [250000,128] x [128,256]. grid 6250 (40 nodes/blk), 256 thr.
__global__ void k_gemm2(const float* __restrict__ W_g2) {
    __shared__ float Ws[32*256];                 // k-chunk of W
    __shared__ __align__(16) float As[32*40];    // transposed: As[kk*40 + m]
    int n0 = blockIdx.x * 40;
    int t = threadIdx.x;
    const float* h1 = g_arena + H1_OFF;
    float2 acc[20];
#pragma unroll
    for (int j = 0; j < 20; j++) acc[j] = make_float2(0.f, 0.f);
    for (int kc = 0; kc < 4; kc++) {
        for (int idx = t; idx < 32*256; idx += 256) Ws[idx] = W_g2[kc*8192 + idx];
        for (int idx = t; idx < 32*40; idx += 256) {
            int m = idx / 32, kk = idx % 32;
            As[kk*40 + m] = h1[(size_t)(n0 + m)*128 + kc*32 + kk];
        }
        __syncthreads();
        for (int kk = 0; kk < 32; kk++) {
            float w = Ws[kk*256 + t];
            float2 w2 = make_float2(w, w);
            const float4* ap = (const float4*)(As + kk*40);
#pragma unroll
            for (int j = 0; j < 10; j++) {
                float4 a = ap[j];
                acc[2*j]   = ffma2(make_float2(a.x, a.y), w2, acc[2*j]);
                acc[2*j+1] = ffma2(make_float2(a.z, a.w), w2, acc[2*j+1]);
            }
        }
        __syncthreads();
    }
    float* out = g_arena + XW2_OFF;
#pragma unroll
    for (int j = 0; j < 10; j++) {
        int m = 4*j;
        out[(size_t)(n0+m  )*256 + t] = acc[2*j].x;
        out[(size_t)(n0+m+1)*256 + t] = acc[2*j].y;
        out[(size_t)(n0+m+2)*256 + t] = acc[2*j+1].x;
        out[(size_t)(n0+m+3)*256 + t] = acc[2*j+1].y;
    }
}

// gather2: 256 channels, writes h2 (aliases arena base). grid TOT_NODES, 256 thr.
__global__ void k_gather2(const float* __restrict__ b_g2) {
    int node = blockIdx.x;
    int g = node / N_;
    int ln = node - g * N_;
    int t = threadIdx.x;
    const float* xw2 = g_arena + XW2_OFF;
    float di = g_dinv[node];
    float acc = di * di * xw2[(size_t)node*256 + t];
    int o0 = g_off[g*(N_+1) + ln];
    int o1 = g_off[g*(N_+1) + ln + 1];
    const int* rows = g_rows + g*E_;
    const float* dv = g_dinv + g*N_;
    size_t gb = (size_t)g * N_ * 256;
    for (int e = o0; e < o1; e++) {
        int r = rows[e];
        acc = fmaf(di * dv[r], xw2[gb + (size_t)r*256 + t], acc);
    }
    acc += b_g2[t];
    g_arena[(size_t)node*256 + t] = leaky(acc);   // h2
}

// max-pool over nodes + FC(256->32, relu) + pe add. grid G_, 256 thr.
__global__ void k_pool(const float* __restrict__ W_fc, const float* __restrict__ b_fc,
                       const float* __restrict__ pe) {
    int g = blockIdx.x;
    int c = threadIdx.x;
    const float* h2 = g_arena;
    __shared__ float ps[256];
    float m = -1e30f;
    size_t base = (size_t)g * N_ * 256 + c;
    for (int n = 0; n < N_; n++) m = fmaxf(m, h2[base + (size_t)n*256]);
    ps[c] = m;
    __syncthreads();
    if (c < 32) {
        float acc = b_fc[c];
        for (int k = 0; k < 256; k++) acc = fmaf(ps[k], W_fc[k*32 + c], acc);
        acc = fmaxf(acc, 0.0f);
        int b = g / 50, s = g - b*50;
        int tk = 2 + s;
        g_xseq[(tk*2 + b)*D_ + c] = acc + pe[tk*D_ + c];
    }
}

// rows 0,1 of xseq: muQ/sigmaQ + pe. 1 block, 128 thr.
__global__ void k_seed(const float* __restrict__ muQ, const float* __restrict__ sigQ,
                       const float* __restrict__ pe) {
    int i = threadIdx.x;           // t*64 + b*32 + d
    int tk = i >> 6;
    int d = i & 31;
    float val = (tk == 0 ? muQ[d] : sigQ[d]) + pe[tk*D_ + d];
    g_xseq[i] = val;
}

// ---------------- transformer ----------------

// qkv = xseq @ in_w^T + in_b. grid 104 (tokens), 96 thr.
__global__ void k_qkv(const float* __restrict__ in_w, const float* __restrict__ in_b, int l) {
    __shared__ float xs[32];
    __shared__ float ws[96*33];
    int tau = blockIdx.x;
    int j = threadIdx.x;
    if (j < 32) xs[j] = g_xseq[tau*32 + j];
    for (int idx = j; idx < 96*32; idx += 96)
        ws[(idx >> 5)*33 + (idx & 31)] = in_w[l*96*32 + idx];
    __syncthreads();
    float acc = in_b[l*96 + j];
#pragma unroll
    for (int d = 0; d < 32; d++) acc = fmaf(xs[d], ws[j*33 + d], acc);
    g_qkv[tau*96 + j] = acc;
}

// per (b,h) attention. grid 8, 64 thr (52 active).
__global__ void k_attn(int l_unused) {
    __shared__ float ks[T_][8];
    __shared__ float vs[T_][8];
    __shared__ float prob[T_][53];
    int bh = blockIdx.x;
    int b = bh >> 2, h = bh & 3;
    int tid = threadIdx.x;
    for (int idx = tid; idx < T_*8; idx += 64) {
        int s = idx >> 3, e = idx & 7;
        ks[s][e] = g_qkv[(s*2 + b)*96 + 32 + h*8 + e];
        vs[s][e] = g_qkv[(s*2 + b)*96 + 64 + h*8 + e];
    }
    __syncthreads();
    if (tid < T_) {
        int t = tid;
        float q[8];
#pragma unroll
        for (int e = 0; e < 8; e++) q[e] = g_qkv[(t*2 + b)*96 + h*8 + e];
        float mx = -1e30f;
        for (int s = 0; s < T_; s++) {
            float sc = 0.f;
#pragma unroll
            for (int e = 0; e < 8; e++) sc = fmaf(q[e], ks[s][e], sc);
            sc *= 0.35355339059327373f;
            prob[t][s] = sc;
            mx = fmaxf(mx, sc);
        }
        float sum = 0.f;
        for (int s = 0; s < T_; s++) {
            float p = expf(prob[t][s] - mx);
            prob[t][s] = p;
            sum += p;
        }
        float inv = 1.0f / sum;
        float o[8];
#pragma unroll
        for (int e = 0; e < 8; e++) o[e] = 0.f;
        for (int s = 0; s < T_; s++) {
            float p = prob[t][s];
#pragma unroll
            for (int e = 0; e < 8; e++) o[e] = fmaf(p, vs[s][e], o[e]);
        }
#pragma unroll
        for (int e = 0; e < 8; e++) g_attn[(t*2 + b)*32 + h*8 + e] = o[e] * inv;
    }
}

// out proj + residual + LN1. grid 104, 32 thr.
__global__ void k_proj_ln1(const float* __restrict__ out_w, const float* __restrict__ out_b,
                           const float* __restrict__ ln1g, const float* __restrict__ ln1b, int l) {
    __shared__ float ow[32*33];
    __shared__ float at[32];
    int tau = blockIdx.x;
    int d = threadIdx.x;
    for (int idx = d; idx < 1024; idx += 32)
        ow[(idx >> 5)*33 + (idx & 31)] = out_w[l*1024 + idx];
    at[d] = g_attn[tau*32 + d];
    __syncthreads();
    float o = out_b[l*32 + d];
#pragma unroll
    for (int c = 0; c < 32; c++) o = fmaf(at[c], ow[d*33 + c], o);
    float val = g_xseq[tau*32 + d] + o;
    float mean = warp_sum(val) * (1.0f/32.0f);
    float dv = val - mean;
    float var = warp_sum(dv*dv) * (1.0f/32.0f);
    float y = dv * rsqrtf(var + 1e-5f) * ln1g[l*32 + d] + ln1b[l*32 + d];
    g_xseq[tau*32 + d] = y;
}

// FF (32->1024 gelu ->32) + residual + LN2. grid 104, 256 thr.
__global__ void k_ff_ln2(const float* __restrict__ w1, const float* __restrict__ b1,
                         const float* __restrict__ w2, const float* __restrict__ b2,
                         const float* __restrict__ ln2g, const float* __restrict__ ln2b, int l) {
    __shared__ __align__(16) float xs[32];
    __shared__ float gs[1024];
    __shared__ float ffo[32];
    int tau = blockIdx.x;
    int t = threadIdx.x;
    if (t < 32) xs[t] = g_xseq[tau*32 + t];
    __syncthreads();
    float4 xr[8];
#pragma unroll
    for (int i = 0; i < 8; i++) xr[i] = *(const float4*)(xs + i*4);
    const float* w1l = w1 + (size_t)l*1024*32;
    const float* b1l = b1 + l*1024;
#pragma unroll
    for (int i = 0; i < 4; i++) {
        int f = t*4 + i;
        float acc = b1l[f];
        const float4* wr = (const float4*)(w1l + (size_t)f*32);
#pragma unroll
        for (int d4 = 0; d4 < 8; d4++) {
            float4 w = wr[d4];
            float4 x = xr[d4];
            acc = fmaf(w.x, x.x, acc);
            acc = fmaf(w.y, x.y, acc);
            acc = fmaf(w.z, x.z, acc);
            acc = fmaf(w.w, x.w, acc);
        }
        gs[f] = 0.5f * acc * (1.0f + erff(acc * 0.70710678118654752f));
    }
    __syncthreads();
    int wid = t >> 5, lane = t & 31;
    const float* w2l = w2 + (size_t)l*32*1024;
#pragma unroll
    for (int pass = 0; pass < 4; pass++) {
        int d = pass*8 + wid;
        const float* wrow = w2l + (size_t)d*1024;
        float p = 0.f;
#pragma unroll 8
        for (int j = 0; j < 32; j++) p = fmaf(gs[j*32 + lane], wrow[j*32 + lane], p);
        p = warp_sum(p);
        if (lane == 0) ffo[d] = p;
    }
    __syncthreads();
    if (t < 32) {
        float val = xs[t] + ffo[t] + b2[l*32 + t];
        float mean = warp_sum(val) * (1.0f/32.0f);
        float dv = val - mean;
        float var = warp_sum(dv*dv) * (1.0f/32.0f);
        float y = dv * rsqrtf(var + 1e-5f) * ln2g[l*32 + t] + ln2b[l*32 + t];
        g_xseq[tau*32 + t] = y;
    }
}

// output: [mu(64) | logvar(64) | xseq(3328)]
__global__ void k_out(float* __restrict__ out, int out_size) {
    int i = blockIdx.x * 256 + threadIdx.x;
    if (i < out_size && i < 3456) {
        out[i] = g_xseq[i < 128 ? i : i - 128];
    }
}

// ---------------- launch ----------------
extern "C" void kernel_launch(void* const* d_in, const int* in_sizes, int n_in,
                              void* d_out, int out_size) {
    const float* v     = (const float*)d_in[0];
    const int*   edge  = (const int*)d_in[2];
    const float* W_emb = (const float*)d_in[3];
    const float* b_emb = (const float*)d_in[4];
    const float* W_g1  = (const float*)d_in[5];
    const float* b_g1  = (const float*)d_in[6];
    const float* W_g2  = (const float*)d_in[7];
    const float* b_g2  = (const float*)d_in[8];
    const float* W_fc  = (const float*)d_in[9];
    const float* b_fc  = (const float*)d_in[10];
    const float* muQ   = (const float*)d_in[11];
    const float* sigQ  = (const float*)d_in[12];
    const float* pe    = (const float*)d_in[13];
    const float* in_w  = (const float*)d_in[14];
    const float* in_b  = (const float*)d_in[15];
    const float* out_w = (const float*)d_in[16];
    const float* out_b = (const float*)d_in[17];
    const float* ln1g  = (const float*)d_in[18];
    const float* ln1b  = (const float*)d_in[19];
    const float* w1    = (const float*)d_in[20];
    const float* b1    = (const float*)d_in[21];
    const float* w2    = (const float*)d_in[22];
    const float* b2    = (const float*)d_in[23];
    const float* ln2g  = (const float*)d_in[24];
    const float* ln2b  = (const float*)d_in[25];

    k_zero<<<(TOT_NODES + 255)/256, 256>>>();
    k_embed_xw1<<<6250, 128>>>(v, W_emb, b_emb, W_g1);
    k_deg<<<(TOT_EDGES + 255)/256, 256>>>(edge);
    k_dinv<<<(TOT_NODES + 255)/256, 256>>>();
    k_scan<<<G_, 256>>>();
    k_fill<<<(TOT_EDGES + 255)/256, 256>>>(edge);
    k_gather1<<<TOT_NODES, 128>>>(b_g1);
    k_gemm2<<<6250, 256>>>(W_g2);
    k_gather2<<<TOT_NODES, 256>>>(b_g2);
    k_pool<<<G_, 256>>>(W_fc, b_fc, pe);
    k_seed<<<1, 128>>>(muQ, sigQ, pe);
    for (int l = 0; l < 4; l++) {
        k_qkv<<<104, 96>>>(in_w, in_b, l);
        k_attn<<<8, 64>>>(l);
        k_proj_ln1<<<104, 32>>>(out_w, out_b, ln1g, ln1b, l);
        k_ff_ln2<<<104, 256>>>(w1, b1, w2, b2, ln2g, ln2b, l);
    }
    k_out<<<(3456 + 255)/256, 256>>>((float*)d_out, out_size);
}

// round 2
// speedup vs baseline: 1.1731x; 1.1731x over previous
#include <cuda_runtime.h>
#include <math.h>
#include <stdint.h>

// ---------------- problem constants ----------------
#define G_  100        // B*S graphs
#define N_  2500       // nodes per graph
#define E_  7500       // edges per graph
#define TOT_NODES 250000
#define TOT_EDGES 750000
#define T_  52         // sequence length (S+2)
#define D_  32         // d_model

// ---------------- scratch (static, allocation-free) ----------------
// arena (floats): x [0,16M) ; xa [16M,32M) ; h1 [32M,64M) ; h1a [64M,96M)
#define X_OFF   0
#define XA_OFF  16000000
#define H1_OFF  32000000
#define H1A_OFF 64000000
__device__ float g_arena[100000000];          // 400 MB
__device__ float g_dinv[TOT_NODES];
__device__ int   g_cnt[TOT_NODES];
__device__ int   g_off[G_*(N_+1)];
__device__ int   g_cur[TOT_NODES];
__device__ int   g_rows[TOT_EDGES];
__device__ int   g_pool[G_*256];
__device__ float g_xseq[T_*2*D_];             // [t][b][d]
__device__ float g_qkv [T_*2*96];
__device__ float g_attn[T_*2*D_];

// ---------------- helpers ----------------
__device__ __forceinline__ float2 ffma2(float2 a, float2 b, float2 c) {
    union U { float2 f; unsigned long long u; } ua, ub, uc;
    ua.f = a; ub.f = b; uc.f = c;
    asm("fma.rn.f32x2 %0, %1, %2, %3;" : "=l"(uc.u) : "l"(ua.u), "l"(ub.u), "l"(uc.u));
    return uc.f;
}

__device__ __forceinline__ float warp_sum(float v) {
#pragma unroll
    for (int o = 16; o; o >>= 1) v += __shfl_xor_sync(0xffffffffu, v, o);
    return v;
}

__device__ __forceinline__ float leaky(float x) {
    return x >= 0.0f ? x : 0.15f * x;
}

// ordered-int encoding for float atomicMax (monotone in float order)
__device__ __forceinline__ int fkey(float f) {
    int i = __float_as_int(f);
    return i >= 0 ? i : (i ^ 0x7FFFFFFF);
}
__device__ __forceinline__ float fdec(int k) {
    return __int_as_float(k >= 0 ? k : (k ^ 0x7FFFFFFF));
}

// ---------------- graph prep ----------------

__global__ void k_init() {
    int i = blockIdx.x * 256 + threadIdx.x;
    if (i < TOT_NODES) g_cnt[i] = 0;
    if (i < G_*256) g_pool[i] = 0x80000000;
}

// x = relu(v @ W_emb + b_emb)   [250K,64]
__global__ void k_embed(const float* __restrict__ v, const float* __restrict__ W_emb,
                        const float* __restrict__ b_emb) {
    int t = threadIdx.x;
    int node = blockIdx.x * 4 + (t >> 6);
    int c = t & 63;
    const float* vp = v + (size_t)node * 3;
    float val = __ldg(b_emb + c);
    val = fmaf(__ldg(vp + 0), __ldg(W_emb + c),       val);
    val = fmaf(__ldg(vp + 1), __ldg(W_emb + 64 + c),  val);
    val = fmaf(__ldg(vp + 2), __ldg(W_emb + 128 + c), val);
    g_arena[X_OFF + (size_t)node*64 + c] = fmaxf(val, 0.0f);
}

__global__ void k_deg(const int* __restrict__ edge) {
    int e = blockIdx.x * 256 + threadIdx.x;
    if (e < TOT_EDGES) {
        int g = e / E_;
        int col = edge[2*e + 1];
        atomicAdd(&g_cnt[g*N_ + col], 1);
    }
}

__global__ void k_dinv() {
    int i = blockIdx.x * 256 + threadIdx.x;
    if (i < TOT_NODES) g_dinv[i] = rsqrtf((float)g_cnt[i] + 1.0f);
}

// per-graph exclusive scan of counts -> CSR offsets. grid G_, 256 thr.
__global__ void k_scan() {
    int g = blockIdx.x;
    int tid = threadIdx.x;
    __shared__ int sm[256];
    int base = tid * 10;
    int loc[10];
    int s = 0;
    if (base < N_) {
#pragma unroll
        for (int i = 0; i < 10; i++) { loc[i] = g_cnt[g*N_ + base + i]; s += loc[i]; }
    }
    sm[tid] = s;
    __syncthreads();
    for (int ofs = 1; ofs < 256; ofs <<= 1) {
        int vv = (tid >= ofs) ? sm[tid - ofs] : 0;
        __syncthreads();
        sm[tid] += vv;
        __syncthreads();
    }
    int excl = sm[tid] - s;
    if (base < N_) {
        int off = excl;
#pragma unroll
        for (int i = 0; i < 10; i++) {
            g_off[g*(N_+1) + base + i] = off;
            g_cur[g*N_ + base + i] = off;
            off += loc[i];
        }
    }
    if (tid == 255) g_off[g*(N_+1) + N_] = sm[255];
}

__global__ void k_fill(const int* __restrict__ edge) {
    int e = blockIdx.x * 256 + threadIdx.x;
    if (e < TOT_EDGES) {
        int g = e / E_;
        int row = edge[2*e];
        int col = edge[2*e + 1];
        int pos = atomicAdd(&g_cur[g*N_ + col], 1);
        g_rows[g*E_ + pos] = row;
    }
}

// ---------------- aggregate-then-GEMM GCN ----------------

// xa = A_hat x  (64 ch). block 256 = 4 nodes x 64 ch. grid 62500.
__global__ void k_agg64() {
    int t = threadIdx.x;
    int node = blockIdx.x * 4 + (t >> 6);
    int c = t & 63;
    int g = node / N_;
    int ln = node - g * N_;
    const float* x = g_arena + X_OFF;
    float di = g_dinv[node];
    float acc = di * di * x[(size_t)node*64 + c];
    int o0 = g_off[g*(N_+1) + ln];
    int o1 = g_off[g*(N_+1) + ln + 1];
    const int* rows = g_rows + g*E_;
    const float* dv = g_dinv + g*N_;
    size_t gb = (size_t)g * N_ * 64;
    for (int e = o0; e < o1; e++) {
        int r = rows[e];
        acc = fmaf(di * dv[r], x[gb + (size_t)r*64 + c], acc);
    }
    g_arena[XA_OFF + (size_t)node*64 + c] = acc;
}

// h1 = leaky(xa @ W_g1 + b_g1)  [250K,128]. 40 nodes/blk, 128 thr. grid 6250.
__global__ void k_gemm1(const float* __restrict__ W_g1, const float* __restrict__ b_g1) {
    __shared__ __align__(16) float As[64*40];   // transposed: As[k*40 + m]
    __shared__ float Ws[64*128];
    int n0 = blockIdx.x * 40;
    int t  = threadIdx.x;
    const float* xa = g_arena + XA_OFF;
    for (int idx = t; idx < 40*64; idx += 128) {
        int m = idx >> 6, k = idx & 63;
        As[k*40 + m] = xa[(size_t)(n0 + m)*64 + k];
    }
    for (int idx = t; idx < 64*128; idx += 128) Ws[idx] = W_g1[idx];
    __syncthreads();

    float2 acc[20];
#pragma unroll
    for (int j = 0; j < 20; j++) acc[j] = make_float2(0.f, 0.f);
    for (int k = 0; k < 64; k++) {
        float w = Ws[k*128 + t];
        float2 w2 = make_float2(w, w);
        const float4* ap = (const float4*)(As + k*40);
#pragma unroll
        for (int j = 0; j < 10; j++) {
            float4 a = ap[j];
            acc[2*j]   = ffma2(make_float2(a.x, a.y), w2, acc[2*j]);
            acc[2*j+1] = ffma2(make_float2(a.z, a.w), w2, acc[2*j+1]);
        }
    }
    float* out = g_arena + H1_OFF;
    float b = b_g1[t];
#pragma unroll
    for (int j = 0; j < 10; j++) {
        int m = 4*j;
        out[(size_t)(n0+m  )*128 + t] = leaky(acc[2*j].x   + b);
        out[(size_t)(n0+m+1)*128 + t] = leaky(acc[2*j].y   + b);
        out[(size_t)(n0+m+2)*128 + t] = leaky(acc[2*j+1].x + b);
        out[(size_t)(n0+m+3)*128 + t] = leaky(acc[2*j+1].y + b);
    }
}

// h1a = A_hat h1  (128 ch). block 256 = 2 nodes x 128 ch. grid 125000.
__global__ void k_agg128() {
    int t = threadIdx.x;
    int node = blockIdx.x * 2 + (t >> 7);
    int c = t & 127;
    int g = node / N_;
    int ln = node - g * N_;
    const float* h1 = g_arena + H1_OFF;
    float di = g_dinv[node];
    float acc = di * di * h1[(size_t)node*128 + c];
    int o0 = g_off[g*(N_+1) + ln];
    int o1 = g_off[g*(N_+1) + ln + 1];
    const int* rows = g_rows + g*E_;
    const float* dv = g_dinv + g*N_;
    size_t gb = (size_t)g * N_ * 128;
    for (int e = o0; e < o1; e++) {
        int r = rows[e];
        acc = fmaf(di * dv[r], h1[gb + (size_t)r*128 + c], acc);
    }
    g_arena[H1A_OFF + (size_t)node*128 + c] = acc;
}

// h2 = leaky(h1a @ W_g2 + b_g2), fused max-pool over nodes via atomicMax.
// 50 nodes/blk (50 | 2500 so tile is within one graph), 256 thr. grid 5000.
__global__ void k_gemm2pool(const float* __restrict__ W_g2, const float* __restrict__ b_g2) {
    __shared__ float Ws[32*256];                 // k-chunk of W
    __shared__ __align__(16) float As[32*56];    // transposed, padded stride 56
    int n0 = blockIdx.x * 50;
    int g = n0 / N_;
    int t = threadIdx.x;
    const float* h1a = g_arena + H1A_OFF;
    float2 acc[25];
#pragma unroll
    for (int j = 0; j < 25; j++) acc[j] = make_float2(0.f, 0.f);
    for (int kc = 0; kc < 4; kc++) {
        for (int idx = t; idx < 32*256; idx += 256) Ws[idx] = W_g2[kc*8192 + idx];
        for (int idx = t; idx < 50*32; idx += 256) {
            int m = idx >> 5, kk = idx & 31;
            As[kk*56 + m] = h1a[(size_t)(n0 + m)*128 + kc*32 + kk];
        }
        __syncthreads();
        for (int kk = 0; kk < 32; kk++) {
            float w = Ws[kk*256 + t];
            float2 w2 = make_float2(w, w);
            const float4* ap = (const float4*)(As + kk*56);
#pragma unroll
            for (int j = 0; j < 12; j++) {
                float4 a = ap[j];
                acc[2*j]   = ffma2(make_float2(a.x, a.y), w2, acc[2*j]);
                acc[2*j+1] = ffma2(make_float2(a.z, a.w), w2, acc[2*j+1]);
            }
            float2 a2 = *(const float2*)(As + kk*56 + 48);
            acc[24] = ffma2(a2, w2, acc[24]);
        }
        __syncthreads();
    }
    float b = b_g2[t];
    float m = -1e30f;
#pragma unroll
    for (int j = 0; j < 25; j++) {
        m = fmaxf(m, leaky(acc[j].x + b));
        m = fmaxf(m, leaky(acc[j].y + b));
    }
    atomicMax(&g_pool[g*256 + t], fkey(m));
}

// decode pool, FC(256->32, relu) + pe; block 0 also seeds mu/sigma rows. grid G_, 256 thr.
__global__ void k_fc(const float* __restrict__ W_fc, const float* __restrict__ b_fc,
                     const float* __restrict__ pe, const float* __restrict__ muQ,
                     const float* __restrict__ sigQ) {
    int g = blockIdx.x;
    int t = threadIdx.x;
    __shared__ float ps[256];
    ps[t] = fdec(g_pool[g*256 + t]);
    __syncthreads();
    if (t < 32) {
        float acc = b_fc[t];
        for (int k = 0; k < 256; k++) acc = fmaf(ps[k], W_fc[k*32 + t], acc);
        acc = fmaxf(acc, 0.0f);
        int b = g / 50, s = g - b*50;
        int tk = 2 + s;
        g_xseq[(tk*2 + b)*D_ + t] = acc + pe[tk*D_ + t];
    }
    if (g == 0 && t >= 128) {
        int i = t - 128;
        int tk = i >> 6;
        int bb = (i >> 5) & 1;
        int d = i & 31;
        g_xseq[(tk*2 + bb)*D_ + d] = (tk == 0 ? muQ[d] : sigQ[d]) + pe[tk*D_ + d];
    }
}

// ---------------- transformer ----------------

// qkv = xseq @ in_w^T + in_b. grid 104 (tokens), 96 thr.
__global__ void k_qkv(const float* __restrict__ in_w, const float* __restrict__ in_b, int l) {
    __shared__ float xs[32];
    __shared__ float ws[96*33];
    int tau = blockIdx.x;
    int j = threadIdx.x;
    if (j < 32) xs[j] = g_xseq[tau*32 + j];
    for (int idx = j; idx < 96*32; idx += 96)
        ws[(idx >> 5)*33 + (idx & 31)] = in_w[l*96*32 + idx];
    __syncthreads();
    float acc = in_b[l*96 + j];
#pragma unroll
    for (int d = 0; d < 32; d++) acc = fmaf(xs[d], ws[j*33 + d], acc);
    g_qkv[tau*96 + j] = acc;
}

// per (b,h) attention. grid 8, 64 thr (52 active).
__global__ void k_attn() {
    __shared__ float ks[T_][8];
    __shared__ float vs[T_][8];
    __shared__ float prob[T_][53];
    int bh = blockIdx.x;
    int b = bh >> 2, h = bh & 3;
    int tid = threadIdx.x;
    for (int idx = tid; idx < T_*8; idx += 64) {
        int s = idx >> 3, e = idx & 7;
        ks[s][e] = g_qkv[(s*2 + b)*96 + 32 + h*8 + e];
        vs[s][e] = g_qkv[(s*2 + b)*96 + 64 + h*8 + e];
    }
    __syncthreads();
    if (tid < T_) {
        int t = tid;
        float q[8];
#pragma unroll
        for (int e = 0; e < 8; e++) q[e] = g_qkv[(t*2 + b)*96 + h*8 + e];
        float mx = -1e30f;
        for (int s = 0; s < T_; s++) {
            float sc = 0.f;
#pragma unroll
            for (int e = 0; e < 8; e++) sc = fmaf(q[e], ks[s][e], sc);
            sc *= 0.35355339059327373f;
            prob[t][s] = sc;
            mx = fmaxf(mx, sc);
        }
        float sum = 0.f;
        for (int s = 0; s < T_; s++) {
            float p = expf(prob[t][s] - mx);
            prob[t][s] = p;
            sum += p;
        }
        float inv = 1.0f / sum;
        float o[8];
#pragma unroll
        for (int e = 0; e < 8; e++) o[e] = 0.f;
        for (int s = 0; s < T_; s++) {
            float p = prob[t][s];
#pragma unroll
            for (int e = 0; e < 8; e++) o[e] = fmaf(p, vs[s][e], o[e]);
        }
#pragma unroll
        for (int e = 0; e < 8; e++) g_attn[(t*2 + b)*32 + h*8 + e] = o[e] * inv;
    }
}

// out proj + residual + LN1. grid 104, 32 thr.
__global__ void k_proj_ln1(const float* __restrict__ out_w, const float* __restrict__ out_b,
                           const float* __restrict__ ln1g, const float* __restrict__ ln1b, int l) {
    __shared__ float ow[32*33];
    __shared__ float at[32];
    int tau = blockIdx.x;
    int d = threadIdx.x;
    for (int idx = d; idx < 1024; idx += 32)
        ow[(idx >> 5)*33 + (idx & 31)] = out_w[l*1024 + idx];
    at[d] = g_attn[tau*32 + d];
    __syncthreads();
    float o = out_b[l*32 + d];
#pragma unroll
    for (int c = 0; c < 32; c++) o = fmaf(at[c], ow[d*33 + c], o);
    float val = g_xseq[tau*32 + d] + o;
    float mean = warp_sum(val) * (1.0f/32.0f);
    float dv = val - mean;
    float var = warp_sum(dv*dv) * (1.0f/32.0f);
    float y = dv * rsqrtf(var + 1e-5f) * ln1g[l*32 + d] + ln1b[l*32 + d];
    g_xseq[tau*32 + d] = y;
}

// FF (32->1024 gelu ->32) + residual + LN2. grid 104, 256 thr.
__global__ void k_ff_ln2(const float* __restrict__ w1, const float* __restrict__ b1,
                         const float* __restrict__ w2, const float* __restrict__ b2,
                         const float* __restrict__ ln2g, const float* __restrict__ ln2b, int l) {
    __shared__ __align__(16) float xs[32];
    __shared__ float gs[1024];
    __shared__ float ffo[32];
    int tau = blockIdx.x;
    int t = threadIdx.x;
    if (t < 32) xs[t] = g_xseq[tau*32 + t];
    __syncthreads();
    float4 xr[8];
#pragma unroll
    for (int i = 0; i < 8; i++) xr[i] = *(const float4*)(xs + i*4);
    const float* w1l = w1 + (size_t)l*1024*32;
    const float* b1l = b1 + l*1024;
#pragma unroll
    for (int i = 0; i < 4; i++) {
        int f = t*4 + i;
        float acc = b1l[f];
        const float4* wr = (const float4*)(w1l + (size_t)f*32);
#pragma unroll
        for (int d4 = 0; d4 < 8; d4++) {
            float4 w = wr[d4];
            float4 x = xr[d4];
            acc = fmaf(w.x, x.x, acc);
            acc = fmaf(w.y, x.y, acc);
            acc = fmaf(w.z, x.z, acc);
            acc = fmaf(w.w, x.w, acc);
        }
        gs[f] = 0.5f * acc * (1.0f + erff(acc * 0.70710678118654752f));
    }
    __syncthreads();
    int wid = t >> 5, lane = t & 31;
    const float* w2l = w2 + (size_t)l*32*1024;
#pragma unroll
    for (int pass = 0; pass < 4; pass++) {
        int d = pass*8 + wid;
        const float* wrow = w2l + (size_t)d*1024;
        float p = 0.f;
#pragma unroll 8
        for (int j = 0; j < 32; j++) p = fmaf(gs[j*32 + lane], wrow[j*32 + lane], p);
        p = warp_sum(p);
        if (lane == 0) ffo[d] = p;
    }
    __syncthreads();
    if (t < 32) {
        float val = xs[t] + ffo[t] + b2[l*32 + t];
        float mean = warp_sum(val) * (1.0f/32.0f);
        float dv = val - mean;
        float var = warp_sum(dv*dv) * (1.0f/32.0f);
        float y = dv * rsqrtf(var + 1e-5f) * ln2g[l*32 + t] + ln2b[l*32 + t];
        g_xseq[tau*32 + t] = y;
    }
}

// output: [mu(64) | logvar(64) | xseq(3328)]
__global__ void k_out(float* __restrict__ out, int out_size) {
    int i = blockIdx.x * 256 + threadIdx.x;
    if (i < out_size && i < 3456) {
        out[i] = g_xseq[i < 128 ? i : i - 128];
    }
}

// ---------------- launch ----------------
extern "C" void kernel_launch(void* const* d_in, const int* in_sizes, int n_in,
                              void* d_out, int out_size) {
    const float* v     = (const float*)d_in[0];
    const int*   edge  = (const int*)d_in[2];
    const float* W_emb = (const float*)d_in[3];
    const float* b_emb = (const float*)d_in[4];
    const float* W_g1  = (const float*)d_in[5];
    const float* b_g1  = (const float*)d_in[6];
    const float* W_g2  = (const float*)d_in[7];
    const float* b_g2  = (const float*)d_in[8];
    const float* W_fc  = (const float*)d_in[9];
    const float* b_fc  = (const float*)d_in[10];
    const float* muQ   = (const float*)d_in[11];
    const float* sigQ  = (const float*)d_in[12];
    const float* pe    = (const float*)d_in[13];
    const float* in_w  = (const float*)d_in[14];
    const float* in_b  = (const float*)d_in[15];
    const float* out_w = (const float*)d_in[16];
    const float* out_b = (const float*)d_in[17];
    const float* ln1g  = (const float*)d_in[18];
    const float* ln1b  = (const float*)d_in[19];
    const float* w1    = (const float*)d_in[20];
    const float* b1    = (const float*)d_in[21];
    const float* w2    = (const float*)d_in[22];
    const float* b2    = (const float*)d_in[23];
    const float* ln2g  = (const float*)d_in[24];
    const float* ln2b  = (const float*)d_in[25];

    k_init<<<(TOT_NODES + 255)/256, 256>>>();
    k_embed<<<62500, 256>>>(v, W_emb, b_emb);
    k_deg<<<(TOT_EDGES + 255)/256, 256>>>(edge);
    k_dinv<<<(TOT_NODES + 255)/256, 256>>>();
    k_scan<<<G_, 256>>>();
    k_fill<<<(TOT_EDGES + 255)/256, 256>>>(edge);
    k_agg64<<<62500, 256>>>();
    k_gemm1<<<6250, 128>>>(W_g1, b_g1);
    k_agg128<<<125000, 256>>>();
    k_gemm2pool<<<5000, 256>>>(W_g2, b_g2);
    k_fc<<<G_, 256>>>(W_fc, b_fc, pe, muQ, sigQ);
    for (int l = 0; l < 4; l++) {
        k_qkv<<<104, 96>>>(in_w, in_b, l);
        k_attn<<<8, 64>>>();
        k_proj_ln1<<<104, 32>>>(out_w, out_b, ln1g, ln1b, l);
        k_ff_ln2<<<104, 256>>>(w1, b1, w2, b2, ln2g, ln2b, l);
    }
    k_out<<<(3456 + 255)/256, 256>>>((float*)d_out, out_size);
}

// round 3
// speedup vs baseline: 1.2415x; 1.0583x over previous
#include <cuda_runtime.h>
#include <math.h>
#include <stdint.h>

// ---------------- problem constants ----------------
#define G_  100        // B*S graphs
#define N_  2500       // nodes per graph
#define E_  7500       // edges per graph
#define TOT_NODES 250000
#define TOT_EDGES 750000
#define T_  52         // sequence length (S+2)
#define D_  32         // d_model

// ---------------- scratch (static, allocation-free) ----------------
__device__ float g_h1[TOT_NODES * 128];       // 128 MB
__device__ float g_dinv[TOT_NODES];
__device__ int   g_cnt[TOT_NODES];
__device__ int   g_off[G_*(N_+1)];
__device__ int   g_cur[TOT_NODES];
__device__ int   g_rows[TOT_EDGES];
__device__ int   g_pool[G_*256];
__device__ float g_xseq[T_*2*D_];             // [t][b][d]
__device__ float g_qkv [T_*2*96];
__device__ float g_attn[T_*2*D_];

// ---------------- helpers ----------------
__device__ __forceinline__ float2 ffma2(float2 a, float2 b, float2 c) {
    union U { float2 f; unsigned long long u; } ua, ub, uc;
    ua.f = a; ub.f = b; uc.f = c;
    asm("fma.rn.f32x2 %0, %1, %2, %3;" : "=l"(uc.u) : "l"(ua.u), "l"(ub.u), "l"(uc.u));
    return uc.f;
}

__device__ __forceinline__ float warp_sum(float v) {
#pragma unroll
    for (int o = 16; o; o >>= 1) v += __shfl_xor_sync(0xffffffffu, v, o);
    return v;
}

__device__ __forceinline__ float leaky(float x) {
    return x >= 0.0f ? x : 0.15f * x;
}

// ordered-int encoding for float atomicMax (monotone in float order)
__device__ __forceinline__ int fkey(float f) {
    int i = __float_as_int(f);
    return i >= 0 ? i : (i ^ 0x7FFFFFFF);
}
__device__ __forceinline__ float fdec(int k) {
    return __int_as_float(k >= 0 ? k : (k ^ 0x7FFFFFFF));
}

// ---------------- graph prep ----------------

__global__ void k_init() {
    int i = blockIdx.x * 256 + threadIdx.x;
    if (i < TOT_NODES) g_cnt[i] = 0;
    if (i < G_*256) g_pool[i] = 0x80000000;
}

__global__ void k_deg(const int* __restrict__ edge) {
    int e = blockIdx.x * 256 + threadIdx.x;
    if (e < TOT_EDGES) {
        int g = e / E_;
        int2 rc = ((const int2*)edge)[e];
        atomicAdd(&g_cnt[g*N_ + rc.y], 1);
    }
}

// per-graph exclusive scan of counts -> CSR offsets; also writes dinv. grid G_, 256 thr.
__global__ void k_scan() {
    int g = blockIdx.x;
    int tid = threadIdx.x;
    __shared__ int sm[256];
    int base = tid * 10;
    int loc[10];
    int s = 0;
    if (base < N_) {
#pragma unroll
        for (int i = 0; i < 10; i++) { loc[i] = g_cnt[g*N_ + base + i]; s += loc[i]; }
    }
    sm[tid] = s;
    __syncthreads();
    for (int ofs = 1; ofs < 256; ofs <<= 1) {
        int vv = (tid >= ofs) ? sm[tid - ofs] : 0;
        __syncthreads();
        sm[tid] += vv;
        __syncthreads();
    }
    int excl = sm[tid] - s;
    if (base < N_) {
        int off = excl;
#pragma unroll
        for (int i = 0; i < 10; i++) {
            g_off[g*(N_+1) + base + i] = off;
            g_cur[g*N_ + base + i] = off;
            g_dinv[g*N_ + base + i] = rsqrtf((float)loc[i] + 1.0f);
            off += loc[i];
        }
    }
    if (tid == 255) g_off[g*(N_+1) + N_] = sm[255];
}

__global__ void k_fill(const int* __restrict__ edge) {
    int e = blockIdx.x * 256 + threadIdx.x;
    if (e < TOT_EDGES) {
        int g = e / E_;
        int2 rc = ((const int2*)edge)[e];
        int pos = atomicAdd(&g_cur[g*N_ + rc.y], 1);
        g_rows[g*E_ + pos] = rc.x;
    }
}

// ---------------- fused GCN layer 1: embed + aggregate + GEMM(64->128) ----------------
// 50 nodes/block (50|2500: block within one graph), 128 threads. grid 5000.
__global__ __launch_bounds__(128) void k_agg_gemm1(
        const float* __restrict__ v, const float* __restrict__ W_emb,
        const float* __restrict__ b_emb, const float* __restrict__ W_g1,
        const float* __restrict__ b_g1) {
    __shared__ __align__(16) float As[50*68];   // As[m*68 + k]
    __shared__ float Ws[64*128];
    int n0 = blockIdx.x * 50;
    int t  = threadIdx.x;
    for (int idx = t; idx < 64*128; idx += 128) Ws[idx] = W_g1[idx];

    // stage 1: x = relu(emb(v)) computed on the fly; As[m][k] = (A_hat x)[n0+m][k]
    {
        int c = t & 63;
        int msub = t >> 6;
        float we0 = __ldg(W_emb + c), we1 = __ldg(W_emb + 64 + c);
        float we2 = __ldg(W_emb + 128 + c), be = __ldg(b_emb + c);
        int gblk = n0 / N_;
        int lnbase = n0 - gblk * N_;
        const int* rows = g_rows + gblk*E_;
        const float* dv = g_dinv + gblk*N_;
        const int* offp = g_off + gblk*(N_+1);
        const float* vg = v + (size_t)gblk * N_ * 3;
#pragma unroll 1
        for (int p = 0; p < 25; p++) {
            int m = p*2 + msub;
            int ln = lnbase + m;
            float di = dv[ln];
            const float* vp = vg + (size_t)ln * 3;
            float xv = fmaxf(fmaf(vp[2], we2, fmaf(vp[1], we1, fmaf(vp[0], we0, be))), 0.f);
            float acc = di * di * xv;
            int o0 = offp[ln], o1 = offp[ln+1];
            for (int e = o0; e < o1; e++) {
                int r = rows[e];
                const float* vq = vg + (size_t)r * 3;
                float xn = fmaxf(fmaf(vq[2], we2, fmaf(vq[1], we1, fmaf(vq[0], we0, be))), 0.f);
                acc = fmaf(di * dv[r], xn, acc);
            }
            As[m*68 + c] = acc;
        }
    }
    __syncthreads();

    // stage 2: h1 = leaky(As @ W_g1 + b), out channel = t
    float2 acc[25];
#pragma unroll
    for (int j = 0; j < 25; j++) acc[j] = make_float2(0.f, 0.f);
    for (int kk = 0; kk < 64; kk += 4) {
        float w0 = Ws[(kk  )*128 + t];
        float w1 = Ws[(kk+1)*128 + t];
        float w2 = Ws[(kk+2)*128 + t];
        float w3 = Ws[(kk+3)*128 + t];
#pragma unroll
        for (int mp = 0; mp < 25; mp++) {
            float4 a0 = *(const float4*)(As + (2*mp  )*68 + kk);
            float4 a1 = *(const float4*)(As + (2*mp+1)*68 + kk);
            acc[mp] = ffma2(make_float2(a0.x, a1.x), make_float2(w0, w0), acc[mp]);
            acc[mp] = ffma2(make_float2(a0.y, a1.y), make_float2(w1, w1), acc[mp]);
            acc[mp] = ffma2(make_float2(a0.z, a1.z), make_float2(w2, w2), acc[mp]);
            acc[mp] = ffma2(make_float2(a0.w, a1.w), make_float2(w3, w3), acc[mp]);
        }
    }
    float b = b_g1[t];
#pragma unroll
    for (int mp = 0; mp < 25; mp++) {
        g_h1[(size_t)(n0 + 2*mp  )*128 + t] = leaky(acc[mp].x + b);
        g_h1[(size_t)(n0 + 2*mp+1)*128 + t] = leaky(acc[mp].y + b);
    }
}

// ---------------- fused GCN layer 2: aggregate + GEMM(128->256) + max-pool ----------------
// 50 nodes/block, 256 threads. grid 5000.
__global__ __launch_bounds__(256) void k_agg_gemm2pool(
        const float* __restrict__ W_g2, const float* __restrict__ b_g2) {
    __shared__ __align__(16) float As[50*132];  // As[m*132 + k]
    __shared__ float Ws[16*256];
    int n0 = blockIdx.x * 50;
    int g = n0 / N_;
    int t = threadIdx.x;

    // stage 1: As[m][k] = (A_hat h1)[n0+m][k]
    {
        int c = t & 127;
        int msub = t >> 7;
        int lnbase = n0 - g * N_;
        const int* rows = g_rows + g*E_;
        const float* dv = g_dinv + g*N_;
        const int* offp = g_off + g*(N_+1);
        const float* h1g = g_h1 + (size_t)g * N_ * 128;
#pragma unroll 1
        for (int p = 0; p < 25; p++) {
            int m = p*2 + msub;
            int ln = lnbase + m;
            float di = dv[ln];
            float acc = di * di * h1g[(size_t)ln*128 + c];
            int o0 = offp[ln], o1 = offp[ln+1];
            for (int e = o0; e < o1; e++) {
                int r = rows[e];
                acc = fmaf(di * dv[r], h1g[(size_t)r*128 + c], acc);
            }
            As[m*132 + c] = acc;
        }
    }
    __syncthreads();

    // stage 2: GEMM 128->256 with k-chunked Ws, fused leaky+bias+max-pool
    float2 acc[25];
#pragma unroll
    for (int j = 0; j < 25; j++) acc[j] = make_float2(0.f, 0.f);
    for (int kc = 0; kc < 8; kc++) {
#pragma unroll
        for (int idx = t; idx < 16*256; idx += 256) Ws[idx] = W_g2[kc*16*256 + idx];
        __syncthreads();
#pragma unroll
        for (int kk = 0; kk < 16; kk += 4) {
            float w0 = Ws[(kk  )*256 + t];
            float w1 = Ws[(kk+1)*256 + t];
            float w2 = Ws[(kk+2)*256 + t];
            float w3 = Ws[(kk+3)*256 + t];
            int kb = kc*16 + kk;
#pragma unroll
            for (int mp = 0; mp < 25; mp++) {
                float4 a0 = *(const float4*)(As + (2*mp  )*132 + kb);
                float4 a1 = *(const float4*)(As + (2*mp+1)*132 + kb);
                acc[mp] = ffma2(make_float2(a0.x, a1.x), make_float2(w0, w0), acc[mp]);
                acc[mp] = ffma2(make_float2(a0.y, a1.y), make_float2(w1, w1), acc[mp]);
                acc[mp] = ffma2(make_float2(a0.z, a1.z), make_float2(w2, w2), acc[mp]);
                acc[mp] = ffma2(make_float2(a0.w, a1.w), make_float2(w3, w3), acc[mp]);
            }
        }
        __syncthreads();
    }
    float b = b_g2[t];
    float m = -1e30f;
#pragma unroll
    for (int mp = 0; mp < 25; mp++) {
        m = fmaxf(m, leaky(acc[mp].x + b));
        m = fmaxf(m, leaky(acc[mp].y + b));
    }
    atomicMax(&g_pool[g*256 + t], fkey(m));
}

// decode pool, FC(256->32, relu) + pe; block 0 also seeds mu/sigma rows. grid G_, 256 thr.
__global__ void k_fc(const float* __restrict__ W_fc, const float* __restrict__ b_fc,
                     const float* __restrict__ pe, const float* __restrict__ muQ,
                     const float* __restrict__ sigQ) {
    int g = blockIdx.x;
    int t = threadIdx.x;
    __shared__ float ps[256];
    ps[t] = fdec(g_pool[g*256 + t]);
    __syncthreads();
    if (t < 32) {
        float acc = b_fc[t];
        for (int k = 0; k < 256; k++) acc = fmaf(ps[k], W_fc[k*32 + t], acc);
        acc = fmaxf(acc, 0.0f);
        int b = g / 50, s = g - b*50;
        int tk = 2 + s;
        g_xseq[(tk*2 + b)*D_ + t] = acc + pe[tk*D_ + t];
    }
    if (g == 0 && t >= 128) {
        int i = t - 128;
        int tk = i >> 6;
        int bb = (i >> 5) & 1;
        int d = i & 31;
        g_xseq[(tk*2 + bb)*D_ + d] = (tk == 0 ? muQ[d] : sigQ[d]) + pe[tk*D_ + d];
    }
}

// ---------------- transformer ----------------

// qkv = xseq @ in_w^T + in_b (layer 0 only). grid 104 (tokens), 96 thr.
__global__ void k_qkv(const float* __restrict__ in_w, const float* __restrict__ in_b, int l) {
    __shared__ float xs[32];
    __shared__ float ws[96*33];
    int tau = blockIdx.x;
    int j = threadIdx.x;
    if (j < 32) xs[j] = g_xseq[tau*32 + j];
    for (int idx = j; idx < 96*32; idx += 96)
        ws[(idx >> 5)*33 + (idx & 31)] = in_w[l*96*32 + idx];
    __syncthreads();
    float acc = in_b[l*96 + j];
#pragma unroll
    for (int d = 0; d < 32; d++) acc = fmaf(xs[d], ws[j*33 + d], acc);
    g_qkv[tau*96 + j] = acc;
}

// per (b,h) attention. grid 8, 64 thr (52 active).
__global__ void k_attn() {
    __shared__ float ks[T_][8];
    __shared__ float vs[T_][8];
    __shared__ float prob[T_][53];
    int bh = blockIdx.x;
    int b = bh >> 2, h = bh & 3;
    int tid = threadIdx.x;
    for (int idx = tid; idx < T_*8; idx += 64) {
        int s = idx >> 3, e = idx & 7;
        ks[s][e] = g_qkv[(s*2 + b)*96 + 32 + h*8 + e];
        vs[s][e] = g_qkv[(s*2 + b)*96 + 64 + h*8 + e];
    }
    __syncthreads();
    if (tid < T_) {
        int t = tid;
        float q[8];
#pragma unroll
        for (int e = 0; e < 8; e++) q[e] = g_qkv[(t*2 + b)*96 + h*8 + e];
        float mx = -1e30f;
        for (int s = 0; s < T_; s++) {
            float sc = 0.f;
#pragma unroll
            for (int e = 0; e < 8; e++) sc = fmaf(q[e], ks[s][e], sc);
            sc *= 0.35355339059327373f;
            prob[t][s] = sc;
            mx = fmaxf(mx, sc);
        }
        float sum = 0.f;
        for (int s = 0; s < T_; s++) {
            float p = expf(prob[t][s] - mx);
            prob[t][s] = p;
            sum += p;
        }
        float inv = 1.0f / sum;
        float o[8];
#pragma unroll
        for (int e = 0; e < 8; e++) o[e] = 0.f;
        for (int s = 0; s < T_; s++) {
            float p = prob[t][s];
#pragma unroll
            for (int e = 0; e < 8; e++) o[e] = fmaf(p, vs[s][e], o[e]);
        }
#pragma unroll
        for (int e = 0; e < 8; e++) g_attn[(t*2 + b)*32 + h*8 + e] = o[e] * inv;
    }
}

// fused: out-proj + residual + LN1 + FF(gelu) + residual + LN2, then
// qkv for layer l+1 (l<3) or final output write (l==3). grid 104, 256 thr.
__global__ void k_block(const float* __restrict__ out_w, const float* __restrict__ out_b,
                        const float* __restrict__ ln1g, const float* __restrict__ ln1b,
                        const float* __restrict__ w1, const float* __restrict__ b1,
                        const float* __restrict__ w2, const float* __restrict__ b2,
                        const float* __restrict__ ln2g, const float* __restrict__ ln2b,
                        const float* __restrict__ in_w, const float* __restrict__ in_b,
                        int l, float* __restrict__ out) {
    __shared__ float ow[32*33];
    __shared__ float wsq[96*33];     // next-layer qkv weights
    __shared__ float at[32];
    __shared__ __align__(16) float xs[32];   // post-LN1
    __shared__ float xin[32];
    __shared__ float gs[1024];
    __shared__ float ffo[32];
    __shared__ __align__(16) float y2[32];   // post-LN2
    int tau = blockIdx.x;
    int t = threadIdx.x;

    for (int idx = t; idx < 1024; idx += 256)
        ow[(idx >> 5)*33 + (idx & 31)] = out_w[l*1024 + idx];
    if (l < 3) {
        for (int idx = t; idx < 96*32; idx += 256)
            wsq[(idx >> 5)*33 + (idx & 31)] = in_w[(l+1)*96*32 + idx];
    }
    if (t < 32) { at[t] = g_attn[tau*32 + t]; xin[t] = g_xseq[tau*32 + t]; }
    __syncthreads();

    if (t < 32) {
        float o = out_b[l*32 + t];
#pragma unroll
        for (int c = 0; c < 32; c++) o = fmaf(at[c], ow[t*33 + c], o);
        float val = xin[t] + o;
        float mean = warp_sum(val) * (1.0f/32.0f);
        float dv = val - mean;
        float var = warp_sum(dv*dv) * (1.0f/32.0f);
        xs[t] = dv * rsqrtf(var + 1e-5f) * ln1g[l*32 + t] + ln1b[l*32 + t];
    }
    __syncthreads();

    // FF: 32 -> 1024 (gelu) -> 32
    float4 xr[8];
#pragma unroll
    for (int i = 0; i < 8; i++) xr[i] = *(const float4*)(xs + i*4);
    const float* w1l = w1 + (size_t)l*1024*32;
    const float* b1l = b1 + l*1024;
#pragma unroll
    for (int i = 0; i < 4; i++) {
        int f = t*4 + i;
        float acc = b1l[f];
        const float4* wr = (const float4*)(w1l + (size_t)f*32);
#pragma unroll
        for (int d4 = 0; d4 < 8; d4++) {
            float4 w = wr[d4];
            float4 x = xr[d4];
            acc = fmaf(w.x, x.x, acc);
            acc = fmaf(w.y, x.y, acc);
            acc = fmaf(w.z, x.z, acc);
            acc = fmaf(w.w, x.w, acc);
        }
        gs[f] = 0.5f * acc * (1.0f + erff(acc * 0.70710678118654752f));
    }
    __syncthreads();
    int wid = t >> 5, lane = t & 31;
    const float* w2l = w2 + (size_t)l*32*1024;
#pragma unroll
    for (int pass = 0; pass < 4; pass++) {
        int d = pass*8 + wid;
        const float* wrow = w2l + (size_t)d*1024;
        float p = 0.f;
#pragma unroll 8
        for (int j = 0; j < 32; j++) p = fmaf(gs[j*32 + lane], wrow[j*32 + lane], p);
        p = warp_sum(p);
        if (lane == 0) ffo[d] = p;
    }
    __syncthreads();
    if (t < 32) {
        float val = xs[t] + ffo[t] + b2[l*32 + t];
        float mean = warp_sum(val) * (1.0f/32.0f);
        float dv = val - mean;
        float var = warp_sum(dv*dv) * (1.0f/32.0f);
        float y = dv * rsqrtf(var + 1e-5f) * ln2g[l*32 + t] + ln2b[l*32 + t];
        g_xseq[tau*32 + t] = y;
        y2[t] = y;
    }
    __syncthreads();

    if (l < 3) {
        if (t < 96) {
            float acc = in_b[(l+1)*96 + t];
#pragma unroll
            for (int d = 0; d < 32; d++) acc = fmaf(y2[d], wsq[t*33 + d], acc);
            g_qkv[tau*96 + t] = acc;
        }
    } else {
        if (t < 32) {
            float y = y2[t];
            out[128 + tau*32 + t] = y;
            if (tau < 4) out[tau*32 + t] = y;
        }
    }
}

// ---------------- launch ----------------
extern "C" void kernel_launch(void* const* d_in, const int* in_sizes, int n_in,
                              void* d_out, int out_size) {
    const float* v     = (const float*)d_in[0];
    const int*   edge  = (const int*)d_in[2];
    const float* W_emb = (const float*)d_in[3];
    const float* b_emb = (const float*)d_in[4];
    const float* W_g1  = (const float*)d_in[5];
    const float* b_g1  = (const float*)d_in[6];
    const float* W_g2  = (const float*)d_in[7];
    const float* b_g2  = (const float*)d_in[8];
    const float* W_fc  = (const float*)d_in[9];
    const float* b_fc  = (const float*)d_in[10];
    const float* muQ   = (const float*)d_in[11];
    const float* sigQ  = (const float*)d_in[12];
    const float* pe    = (const float*)d_in[13];
    const float* in_w  = (const float*)d_in[14];
    const float* in_b  = (const float*)d_in[15];
    const float* out_w = (const float*)d_in[16];
    const float* out_b = (const float*)d_in[17];
    const float* ln1g  = (const float*)d_in[18];
    const float* ln1b  = (const float*)d_in[19];
    const float* w1    = (const float*)d_in[20];
    const float* b1    = (const float*)d_in[21];
    const float* w2    = (const float*)d_in[22];
    const float* b2    = (const float*)d_in[23];
    const float* ln2g  = (const float*)d_in[24];
    const float* ln2b  = (const float*)d_in[25];

    k_init<<<(TOT_NODES + 255)/256, 256>>>();
    k_deg<<<(TOT_EDGES + 255)/256, 256>>>(edge);
    k_scan<<<G_, 256>>>();
    k_fill<<<(TOT_EDGES + 255)/256, 256>>>(edge);
    k_agg_gemm1<<<5000, 128>>>(v, W_emb, b_emb, W_g1, b_g1);
    k_agg_gemm2pool<<<5000, 256>>>(W_g2, b_g2);
    k_fc<<<G_, 256>>>(W_fc, b_fc, pe, muQ, sigQ);
    k_qkv<<<104, 96>>>(in_w, in_b, 0);
    for (int l = 0; l < 4; l++) {
        k_attn<<<8, 64>>>();
        k_block<<<104, 256>>>(out_w, out_b, ln1g, ln1b, w1, b1, w2, b2,
                              ln2g, ln2b, in_w, in_b, l, (float*)d_out);
    }
}

// round 5
// speedup vs baseline: 1.2713x; 1.0240x over previous
#include <cuda_runtime.h>
#include <math.h>
#include <stdint.h>

// ---------------- problem constants ----------------
#define G_  100        // B*S graphs
#define N_  2500       // nodes per graph
#define E_  7500       // edges per graph
#define TOT_NODES 250000
#define TOT_EDGES 750000
#define T_  52         // sequence length (S+2)
#define D_  32         // d_model
#define NB_ 104        // transformer blocks (tokens)

// ---------------- scratch (static, allocation-free) ----------------
__device__ float g_h1[TOT_NODES * 128];       // 128 MB
__device__ float g_dinv[TOT_NODES];
__device__ int   g_cnt[TOT_NODES];
__device__ int   g_off[G_*(N_+1)];
__device__ int   g_cur[TOT_NODES];
__device__ int   g_rows[TOT_EDGES];
__device__ int   g_pool[G_*256];
__device__ float g_xseq[T_*2*D_];             // [t][b][d]
__device__ float g_qkvbuf[2][NB_*96];
__device__ int   g_bar_cnt;
__device__ volatile int g_bar_gen;

// ---------------- helpers ----------------
__device__ __forceinline__ float2 ffma2(float2 a, float2 b, float2 c) {
    union U { float2 f; unsigned long long u; } ua, ub, uc;
    ua.f = a; ub.f = b; uc.f = c;
    asm("fma.rn.f32x2 %0, %1, %2, %3;" : "=l"(uc.u) : "l"(ua.u), "l"(ub.u), "l"(uc.u));
    return uc.f;
}

__device__ __forceinline__ float warp_sum(float v) {
#pragma unroll
    for (int o = 16; o; o >>= 1) v += __shfl_xor_sync(0xffffffffu, v, o);
    return v;
}
__device__ __forceinline__ float warp_max(float v) {
#pragma unroll
    for (int o = 16; o; o >>= 1) v = fmaxf(v, __shfl_xor_sync(0xffffffffu, v, o));
    return v;
}

__device__ __forceinline__ float leaky(float x) {
    return x >= 0.0f ? x : 0.15f * x;
}

// ordered-int encoding for float atomicMax (monotone in float order)
__device__ __forceinline__ int fkey(float f) {
    int i = __float_as_int(f);
    return i >= 0 ? i : (i ^ 0x7FFFFFFF);
}
__device__ __forceinline__ float fdec(int k) {
    return __int_as_float(k >= 0 ? k : (k ^ 0x7FFFFFFF));
}

// ---------------- graph prep ----------------

__global__ void k_init() {
    int i = blockIdx.x * 256 + threadIdx.x;
    if (i < TOT_NODES) g_cnt[i] = 0;
    if (i < G_*256) g_pool[i] = 0x80000000;
}

__global__ void k_deg(const int* __restrict__ edge) {
    int e = blockIdx.x * 256 + threadIdx.x;
    if (e < TOT_EDGES) {
        int g = e / E_;
        int2 rc = ((const int2*)edge)[e];
        atomicAdd(&g_cnt[g*N_ + rc.y], 1);
    }
}

// per-graph exclusive scan of counts -> CSR offsets; also writes dinv. grid G_, 256 thr.
__global__ void k_scan() {
    int g = blockIdx.x;
    int tid = threadIdx.x;
    __shared__ int sm[256];
    int base = tid * 10;
    int loc[10];
    int s = 0;
    if (base < N_) {
#pragma unroll
        for (int i = 0; i < 10; i++) { loc[i] = g_cnt[g*N_ + base + i]; s += loc[i]; }
    }
    sm[tid] = s;
    __syncthreads();
    for (int ofs = 1; ofs < 256; ofs <<= 1) {
        int vv = (tid >= ofs) ? sm[tid - ofs] : 0;
        __syncthreads();
        sm[tid] += vv;
        __syncthreads();
    }
    int excl = sm[tid] - s;
    if (base < N_) {
        int off = excl;
#pragma unroll
        for (int i = 0; i < 10; i++) {
            g_off[g*(N_+1) + base + i] = off;
            g_cur[g*N_ + base + i] = off;
            g_dinv[g*N_ + base + i] = rsqrtf((float)loc[i] + 1.0f);
            off += loc[i];
        }
    }
    if (tid == 255) g_off[g*(N_+1) + N_] = sm[255];
}

__global__ void k_fill(const int* __restrict__ edge) {
    int e = blockIdx.x * 256 + threadIdx.x;
    if (e < TOT_EDGES) {
        int g = e / E_;
        int2 rc = ((const int2*)edge)[e];
        int pos = atomicAdd(&g_cur[g*N_ + rc.y], 1);
        g_rows[g*E_ + pos] = rc.x;
    }
}

// ---------------- fused GCN layer 1: embed + aggregate + GEMM(64->128) ----------------
// 50 nodes/block, 128 threads. grid 5000. Edge data staged in smem; W chunked 16 rows.
#define CAP1 384
__global__ __launch_bounds__(128) void k_agg_gemm1(
        const float* __restrict__ v, const float* __restrict__ W_emb,
        const float* __restrict__ b_emb, const float* __restrict__ W_g1,
        const float* __restrict__ b_g1) {
    __shared__ __align__(16) float As[50*68];   // As[m*68 + k]   13600 B
    __shared__ float Ws[16*128];                //                 8192 B
    __shared__ float v0s[CAP1], v1s[CAP1], v2s[CAP1], nrs[CAP1];  // 6144 B
    __shared__ int   off_s[51];
    __shared__ float dnode[50];
    __shared__ float vself[50*3];
    int n0 = blockIdx.x * 50;
    int g = n0 / N_;
    int lnbase = n0 - g * N_;
    int t  = threadIdx.x;

    const float* dv = g_dinv + g*N_;
    const float* vg = v + (size_t)g * N_ * 3;
    if (t < 51) off_s[t] = g_off[g*(N_+1) + lnbase + t];
    if (t < 50) dnode[t] = dv[lnbase + t];
    for (int idx = t; idx < 150; idx += 128) vself[idx] = vg[(size_t)lnbase*3 + idx];
    __syncthreads();
    int e0 = off_s[0];
    int ecnt = off_s[50] - e0;
    const int* rowsg = g_rows + g*E_ + e0;
    for (int i = t; i < ecnt && i < CAP1; i += 128) {
        int r = rowsg[i];
        const float* vp = vg + (size_t)r*3;
        v0s[i] = vp[0]; v1s[i] = vp[1]; v2s[i] = vp[2];
        nrs[i] = dv[r];
    }
    __syncthreads();

    // stage 1: As[m][c] = (A_hat relu(emb(v)))[n0+m][c]
    {
        int c = t & 63;
        int msub = t >> 6;
        float we0 = __ldg(W_emb + c), we1 = __ldg(W_emb + 64 + c);
        float we2 = __ldg(W_emb + 128 + c), be = __ldg(b_emb + c);
#pragma unroll 1
        for (int p = 0; p < 25; p++) {
            int m = p*2 + msub;
            float di = dnode[m];
            float xv = fmaxf(fmaf(vself[m*3+2], we2,
                         fmaf(vself[m*3+1], we1, fmaf(vself[m*3], we0, be))), 0.f);
            float acc = di * di * xv;
            int o0 = off_s[m] - e0, o1 = off_s[m+1] - e0;
            for (int e = o0; e < o1; e++) {
                float a0, a1, a2, nr;
                if (e < CAP1) { a0 = v0s[e]; a1 = v1s[e]; a2 = v2s[e]; nr = nrs[e]; }
                else {
                    int r = rowsg[e];
                    const float* vq = vg + (size_t)r*3;
                    a0 = vq[0]; a1 = vq[1]; a2 = vq[2]; nr = dv[r];
                }
                float xn = fmaxf(fmaf(a2, we2, fmaf(a1, we1, fmaf(a0, we0, be))), 0.f);
                acc = fmaf(di * nr, xn, acc);
            }
            As[m*68 + c] = acc;
        }
    }
    __syncthreads();

    // stage 2: h1 = leaky(As @ W_g1 + b), out channel = t, W chunked 16 k-rows
    float2 acc[25];
#pragma unroll
    for (int j = 0; j < 25; j++) acc[j] = make_float2(0.f, 0.f);
    for (int kc = 0; kc < 4; kc++) {
#pragma unroll
        for (int idx = t; idx < 16*128; idx += 128) Ws[idx] = W_g1[kc*16*128 + idx];
        __syncthreads();
#pragma unroll
        for (int kk = 0; kk < 16; kk += 4) {
            float w0 = Ws[(kk  )*128 + t];
            float w1 = Ws[(kk+1)*128 + t];
            float w2 = Ws[(kk+2)*128 + t];
            float w3 = Ws[(kk+3)*128 + t];
            int kb = kc*16 + kk;
#pragma unroll
            for (int mp = 0; mp < 25; mp++) {
                float4 a0 = *(const float4*)(As + (2*mp  )*68 + kb);
                float4 a1 = *(const float4*)(As + (2*mp+1)*68 + kb);
                acc[mp] = ffma2(make_float2(a0.x, a1.x), make_float2(w0, w0), acc[mp]);
                acc[mp] = ffma2(make_float2(a0.y, a1.y), make_float2(w1, w1), acc[mp]);
                acc[mp] = ffma2(make_float2(a0.z, a1.z), make_float2(w2, w2), acc[mp]);
                acc[mp] = ffma2(make_float2(a0.w, a1.w), make_float2(w3, w3), acc[mp]);
            }
        }
        __syncthreads();
    }
    float b = b_g1[t];
#pragma unroll
    for (int mp = 0; mp < 25; mp++) {
        g_h1[(size_t)(n0 + 2*mp  )*128 + t] = leaky(acc[mp].x + b);
        g_h1[(size_t)(n0 + 2*mp+1)*128 + t] = leaky(acc[mp].y + b);
    }
}

// ---------------- fused GCN layer 2: aggregate + GEMM(128->256) + max-pool ----------------
// 50 nodes/block, 256 threads. grid 5000. Edge indices staged in smem.
#define CAP2 384
__global__ __launch_bounds__(256) void k_agg_gemm2pool(
        const float* __restrict__ W_g2, const float* __restrict__ b_g2) {
    __shared__ __align__(16) float As[50*132];  // 26400 B
    __shared__ float Ws[16*256];                // 16384 B
    __shared__ int   rows_s[CAP2];              //  1536 B
    __shared__ float nrm_s[CAP2];               //  1536 B
    __shared__ int   off_s[51];
    __shared__ float dnode[50];
    int n0 = blockIdx.x * 50;
    int g = n0 / N_;
    int lnbase = n0 - g * N_;
    int t = threadIdx.x;

    const float* dv = g_dinv + g*N_;
    if (t < 51) off_s[t] = g_off[g*(N_+1) + lnbase + t];
    if (t < 50) dnode[t] = dv[lnbase + t];
    __syncthreads();
    int e0 = off_s[0];
    int ecnt = off_s[50] - e0;
    const int* rowsg = g_rows + g*E_ + e0;
    for (int i = t; i < ecnt && i < CAP2; i += 256) {
        int r = rowsg[i];
        rows_s[i] = r;
        nrm_s[i] = dv[r];
    }
    __syncthreads();

    // stage 1: As[m][c] = (A_hat h1)[n0+m][c]
    {
        int c = t & 127;
        int msub = t >> 7;
        const float* h1g = g_h1 + (size_t)g * N_ * 128;
#pragma unroll 1
        for (int p = 0; p < 25; p++) {
            int m = p*2 + msub;
            float di = dnode[m];
            float acc = di * di * h1g[(size_t)(lnbase+m)*128 + c];
            int o0 = off_s[m] - e0, o1 = off_s[m+1] - e0;
            int e = o0;
            for (; e + 1 < o1; e += 2) {
                int r0 = (e   < CAP2) ? rows_s[e]   : rowsg[e];
                int r1 = (e+1 < CAP2) ? rows_s[e+1] : rowsg[e+1];
                float w0 = (e   < CAP2) ? nrm_s[e]   : dv[r0];
                float w1 = (e+1 < CAP2) ? nrm_s[e+1] : dv[r1];
                float a0 = h1g[(size_t)r0*128 + c];
                float a1 = h1g[(size_t)r1*128 + c];
                acc = fmaf(di * w0, a0, acc);
                acc = fmaf(di * w1, a1, acc);
            }
            if (e < o1) {
                int r0 = (e < CAP2) ? rows_s[e] : rowsg[e];
                float w0 = (e < CAP2) ? nrm_s[e] : dv[r0];
                acc = fmaf(di * w0, h1g[(size_t)r0*128 + c], acc);
            }
            As[m*132 + c] = acc;
        }
    }
    __syncthreads();

    // stage 2: GEMM 128->256 with k-chunked Ws, fused leaky+bias+max-pool
    float2 acc[25];
#pragma unroll
    for (int j = 0; j < 25; j++) acc[j] = make_float2(0.f, 0.f);
    for (int kc = 0; kc < 8; kc++) {
#pragma unroll
        for (int idx = t; idx < 16*256; idx += 256) Ws[idx] = W_g2[kc*16*256 + idx];
        __syncthreads();
#pragma unroll
        for (int kk = 0; kk < 16; kk += 4) {
            float w0 = Ws[(kk  )*256 + t];
            float w1 = Ws[(kk+1)*256 + t];
            float w2 = Ws[(kk+2)*256 + t];
            float w3 = Ws[(kk+3)*256 + t];
            int kb = kc*16 + kk;
#pragma unroll
            for (int mp = 0; mp < 25; mp++) {
                float4 a0 = *(const float4*)(As + (2*mp  )*132 + kb);
                float4 a1 = *(const float4*)(As + (2*mp+1)*132 + kb);
                acc[mp] = ffma2(make_float2(a0.x, a1.x), make_float2(w0, w0), acc[mp]);
                acc[mp] = ffma2(make_float2(a0.y, a1.y), make_float2(w1, w1), acc[mp]);
                acc[mp] = ffma2(make_float2(a0.z, a1.z), make_float2(w2, w2), acc[mp]);
                acc[mp] = ffma2(make_float2(a0.w, a1.w), make_float2(w3, w3), acc[mp]);
            }
        }
        __syncthreads();
    }
    float b = b_g2[t];
    float m = -1e30f;
#pragma unroll
    for (int mp = 0; mp < 25; mp++) {
        m = fmaxf(m, leaky(acc[mp].x + b));
        m = fmaxf(m, leaky(acc[mp].y + b));
    }
    atomicMax(&g_pool[g*256 + t], fkey(m));
}

// decode pool, FC(256->32, relu) + pe; seeds mu/sigma rows; resets grid barrier. grid G_, 256 thr.
__global__ void k_fc(const float* __restrict__ W_fc, const float* __restrict__ b_fc,
                     const float* __restrict__ pe, const float* __restrict__ muQ,
                     const float* __restrict__ sigQ) {
    int g = blockIdx.x;
    int t = threadIdx.x;
    __shared__ float ps[256];
    ps[t] = fdec(g_pool[g*256 + t]);
    __syncthreads();
    if (t < 32) {
        float acc = b_fc[t];
        for (int k = 0; k < 256; k++) acc = fmaf(ps[k], W_fc[k*32 + t], acc);
        acc = fmaxf(acc, 0.0f);
        int b = g / 50, s = g - b*50;
        int tk = 2 + s;
        g_xseq[(tk*2 + b)*D_ + t] = acc + pe[tk*D_ + t];
    }
    if (g == 0 && t >= 128 && t < 256) {
        int i = t - 128;
        if (i < 128) {
            int tk = i >> 6;
            int bb = (i >> 5) & 1;
            int d = i & 31;
            g_xseq[(tk*2 + bb)*D_ + d] = (tk == 0 ? muQ[d] : sigQ[d]) + pe[tk*D_ + d];
        }
    }
    if (g == 0 && t == 64) { g_bar_cnt = 0; g_bar_gen = 0; }
}

// ---------------- single-kernel transformer (104 resident blocks, grid barrier) ----------------

__device__ __forceinline__ void grid_bar(int target) {
    __syncthreads();
    if (threadIdx.x == 0) {
        __threadfence();
        int v = atomicAdd(&g_bar_cnt, 1);
        if (v + 1 == NB_ * target) {
            g_bar_gen = target;
        } else {
            while (g_bar_gen < target) { }
        }
        __threadfence();
    }
    __syncthreads();
}

__global__ __launch_bounds__(256) void k_transformer(
        const float* __restrict__ in_w, const float* __restrict__ in_b,
        const float* __restrict__ out_w, const float* __restrict__ out_b,
        const float* __restrict__ ln1g, const float* __restrict__ ln1b,
        const float* __restrict__ w1, const float* __restrict__ b1,
        const float* __restrict__ w2, const float* __restrict__ b2,
        const float* __restrict__ ln2g, const float* __restrict__ ln2b,
        float* __restrict__ out) {
    __shared__ float wsq[96*33];             // qkv weights (this layer)
    __shared__ float ow[32*33];              // out-proj weights
    __shared__ __align__(16) float xv[32];   // current token vector
    __shared__ float at[32];                 // attention output
    __shared__ __align__(16) float xs[32];   // post-LN1
    __shared__ float gs[1024];
    __shared__ float ffo[32];
    int tau = blockIdx.x;
    int t = threadIdx.x;
    int wid = t >> 5, lane = t & 31;
    int b = tau & 1;

    if (t < 32) xv[t] = g_xseq[tau*32 + t];

    for (int l = 0; l < 4; l++) {
        // load this layer's qkv + proj weights
        for (int idx = t; idx < 96*32; idx += 256)
            wsq[(idx >> 5)*33 + (idx & 31)] = in_w[l*96*32 + idx];
        for (int idx = t; idx < 1024; idx += 256)
            ow[(idx >> 5)*33 + (idx & 31)] = out_w[l*1024 + idx];
        __syncthreads();

        // qkv for own token -> buffer l&1
        float* qk = g_qkvbuf[l & 1];
        if (t < 96) {
            float acc = in_b[l*96 + t];
#pragma unroll
            for (int d = 0; d < 32; d++) acc = fmaf(xv[d], wsq[t*33 + d], acc);
            qk[tau*96 + t] = acc;
        }
        grid_bar(l + 1);   // all tokens' qkv visible

        // attention: warp h handles head h; lanes cover s = lane, lane+32
        if (wid < 4) {
            int h = wid;
            float4 qa = *(const float4*)(qk + tau*96 + h*8);
            float4 qb = *(const float4*)(qk + tau*96 + h*8 + 4);
            int s0 = lane, s1 = lane + 32;
            const float* k0 = qk + (s0*2 + b)*96 + 32 + h*8;
            float4 ka = *(const float4*)(k0);
            float4 kb = *(const float4*)(k0 + 4);
            float sc0 = (qa.x*ka.x + qa.y*ka.y + qa.z*ka.z + qa.w*ka.w +
                         qb.x*kb.x + qb.y*kb.y + qb.z*kb.z + qb.w*kb.w) * 0.35355339059327373f;
            const float* v0p = qk + (s0*2 + b)*96 + 64 + h*8;
            float4 va = *(const float4*)(v0p);
            float4 vb = *(const float4*)(v0p + 4);
            float sc1 = -1e30f;
            float4 wa = make_float4(0.f,0.f,0.f,0.f), wb = wa;
            if (s1 < T_) {
                const float* k1 = qk + (s1*2 + b)*96 + 32 + h*8;
                float4 kc = *(const float4*)(k1);
                float4 kd = *(const float4*)(k1 + 4);
                sc1 = (qa.x*kc.x + qa.y*kc.y + qa.z*kc.z + qa.w*kc.w +
                       qb.x*kd.x + qb.y*kd.y + qb.z*kd.z + qb.w*kd.w) * 0.35355339059327373f;
                const float* v1p = qk + (s1*2 + b)*96 + 64 + h*8;
                wa = *(const float4*)(v1p);
                wb = *(const float4*)(v1p + 4);
            }
            float mx = warp_max(fmaxf(sc0, sc1));
            float p0 = expf(sc0 - mx);
            float p1 = (s1 < T_) ? expf(sc1 - mx) : 0.f;
            float sum = warp_sum(p0 + p1);
            float o[8];
            o[0] = p0*va.x + p1*wa.x;  o[1] = p0*va.y + p1*wa.y;
            o[2] = p0*va.z + p1*wa.z;  o[3] = p0*va.w + p1*wa.w;
            o[4] = p0*vb.x + p1*wb.x;  o[5] = p0*vb.y + p1*wb.y;
            o[6] = p0*vb.z + p1*wb.z;  o[7] = p0*vb.w + p1*wb.w;
#pragma unroll
            for (int e = 0; e < 8; e++) o[e] = warp_sum(o[e]);
            if (lane == 0) {
                float inv = 1.0f / sum;
#pragma unroll
                for (int e = 0; e < 8; e++) at[h*8 + e] = o[e] * inv;
            }
        }
        __syncthreads();

        // out-proj + residual + LN1
        if (t < 32) {
            float o = out_b[l*32 + t];
#pragma unroll
            for (int c = 0; c < 32; c++) o = fmaf(at[c], ow[t*33 + c], o);
            float val = xv[t] + o;
            float mean = warp_sum(val) * (1.0f/32.0f);
            float dvv = val - mean;
            float var = warp_sum(dvv*dvv) * (1.0f/32.0f);
            xs[t] = dvv * rsqrtf(var + 1e-5f) * ln1g[l*32 + t] + ln1b[l*32 + t];
        }
        __syncthreads();

        // FF: 32 -> 1024 (gelu) -> 32
        float4 xr[8];
#pragma unroll
        for (int i = 0; i < 8; i++) xr[i] = *(const float4*)(xs + i*4);
        const float* w1l = w1 + (size_t)l*1024*32;
        const float* b1l = b1 + l*1024;
#pragma unroll
        for (int i = 0; i < 4; i++) {
            int f = t*4 + i;
            float acc = b1l[f];
            const float4* wr = (const float4*)(w1l + (size_t)f*32);
#pragma unroll
            for (int d4 = 0; d4 < 8; d4++) {
                float4 w = wr[d4];
                float4 x = xr[d4];
                acc = fmaf(w.x, x.x, acc);
                acc = fmaf(w.y, x.y, acc);
                acc = fmaf(w.z, x.z, acc);
                acc = fmaf(w.w, x.w, acc);
            }
            gs[f] = 0.5f * acc * (1.0f + erff(acc * 0.70710678118654752f));
        }
        __syncthreads();
        const float* w2l = w2 + (size_t)l*32*1024;
#pragma unroll
        for (int pass = 0; pass < 4; pass++) {
            int d = pass*8 + wid;
            const float* wrow = w2l + (size_t)d*1024;
            float p = 0.f;
#pragma unroll 8
            for (int j = 0; j < 32; j++) p = fmaf(gs[j*32 + lane], wrow[j*32 + lane], p);
            p = warp_sum(p);
            if (lane == 0) ffo[d] = p;
        }
        __syncthreads();
        if (t < 32) {
            float val = xs[t] + ffo[t] + b2[l*32 + t];
            float mean = warp_sum(val) * (1.0f/32.0f);
            float dvv = val - mean;
            float var = warp_sum(dvv*dvv) * (1.0f/32.0f);
            xv[t] = dvv * rsqrtf(var + 1e-5f) * ln2g[l*32 + t] + ln2b[l*32 + t];
        }
        __syncthreads();
    }

    // output: [mu(64) | logvar(64) | xseq(3328)]
    if (t < 32) {
        float y = xv[t];
        out[128 + tau*32 + t] = y;
        if (tau < 4) out[tau*32 + t] = y;
    }
}

// ---------------- launch ----------------
extern "C" void kernel_launch(void* const* d_in, const int* in_sizes, int n_in,
                              void* d_out, int out_size) {
    const float* v     = (const float*)d_in[0];
    const int*   edge  = (const int*)d_in[2];
    const float* W_emb = (const float*)d_in[3];
    const float* b_emb = (const float*)d_in[4];
    const float* W_g1  = (const float*)d_in[5];
    const float* b_g1  = (const float*)d_in[6];
    const float* W_g2  = (const float*)d_in[7];
    const float* b_g2  = (const float*)d_in[8];
    const float* W_fc  = (const float*)d_in[9];
    const float* b_fc  = (const float*)d_in[10];
    const float* muQ   = (const float*)d_in[11];
    const float* sigQ  = (const float*)d_in[12];
    const float* pe    = (const float*)d_in[13];
    const float* in_w  = (const float*)d_in[14];
    const float* in_b  = (const float*)d_in[15];
    const float* out_w = (const float*)d_in[16];
    const float* out_b = (const float*)d_in[17];
    const float* ln1g  = (const float*)d_in[18];
    const float* ln1b  = (const float*)d_in[19];
    const float* w1    = (const float*)d_in[20];
    const float* b1    = (const float*)d_in[21];
    const float* w2    = (const float*)d_in[22];
    const float* b2    = (const float*)d_in[23];
    const float* ln2g  = (const float*)d_in[24];
    const float* ln2b  = (const float*)d_in[25];

    k_init<<<(TOT_NODES + 255)/256, 256>>>();
    k_deg<<<(TOT_EDGES + 255)/256, 256>>>(edge);
    k_scan<<<G_, 256>>>();
    k_fill<<<(TOT_EDGES + 255)/256, 256>>>(edge);
    k_agg_gemm1<<<5000, 128>>>(v, W_emb, b_emb, W_g1, b_g1);
    k_agg_gemm2pool<<<5000, 256>>>(W_g2, b_g2);
    k_fc<<<G_, 256>>>(W_fc, b_fc, pe, muQ, sigQ);
    k_transformer<<<NB_, 256>>>(in_w, in_b, out_w, out_b, ln1g, ln1b,
                                w1, b1, w2, b2, ln2g, ln2b, (float*)d_out);
}

// round 6
// speedup vs baseline: 1.3294x; 1.0457x over previous
#include <cuda_runtime.h>
#include <math.h>
#include <stdint.h>

// ---------------- problem constants ----------------
#define G_  100        // B*S graphs
#define N_  2500       // nodes per graph
#define E_  7500       // edges per graph
#define TOT_NODES 250000
#define TOT_EDGES 750000
#define T_  52         // sequence length (S+2)
#define D_  32         // d_model
#define NB_ 104        // transformer blocks (tokens)

// ---------------- scratch (static, allocation-free) ----------------
__device__ float g_h1[TOT_NODES * 128];       // 128 MB
__device__ float g_dinv[TOT_NODES];
__device__ int   g_off[G_*(N_+1)];
__device__ int   g_rows[TOT_EDGES];
__device__ int   g_pool[G_*256];
__device__ float g_xseq[T_*2*D_];             // [t][b][d]
__device__ float g_qkvbuf[2][NB_*96];
__device__ int   g_bar_cnt;
__device__ volatile int g_bar_gen;

// ---------------- helpers ----------------
__device__ __forceinline__ float2 ffma2(float2 a, float2 b, float2 c) {
    union U { float2 f; unsigned long long u; } ua, ub, uc;
    ua.f = a; ub.f = b; uc.f = c;
    asm("fma.rn.f32x2 %0, %1, %2, %3;" : "=l"(uc.u) : "l"(ua.u), "l"(ub.u), "l"(uc.u));
    return uc.f;
}

__device__ __forceinline__ float warp_sum(float v) {
#pragma unroll
    for (int o = 16; o; o >>= 1) v += __shfl_xor_sync(0xffffffffu, v, o);
    return v;
}
__device__ __forceinline__ float warp_max(float v) {
#pragma unroll
    for (int o = 16; o; o >>= 1) v = fmaxf(v, __shfl_xor_sync(0xffffffffu, v, o));
    return v;
}

__device__ __forceinline__ float leaky(float x) {
    return x >= 0.0f ? x : 0.15f * x;
}

// ordered-int encoding for float atomicMax (monotone in float order)
__device__ __forceinline__ int fkey(float f) {
    int i = __float_as_int(f);
    return i >= 0 ? i : (i ^ 0x7FFFFFFF);
}
__device__ __forceinline__ float fdec(int k) {
    return __int_as_float(k >= 0 ? k : (k ^ 0x7FFFFFFF));
}

// ---------------- fused graph prep: count + scan + dinv + scatter + pool init ----------------
// block = graph. 100 blocks, 256 threads.
__global__ __launch_bounds__(256) void k_prep(const int* __restrict__ edge) {
    __shared__ int cnt[N_];       // 10000 B
    __shared__ int cur[N_];       // 10000 B
    __shared__ int sm[256];
    int g = blockIdx.x;
    int t = threadIdx.x;
    for (int i = t; i < N_; i += 256) cnt[i] = 0;
    __syncthreads();

    const int2* eg = (const int2*)edge + (size_t)g * E_;
    for (int i = t; i < E_; i += 256) {
        int2 rc = eg[i];
        atomicAdd(&cnt[rc.y], 1);
    }
    __syncthreads();

    // exclusive scan over 2500 counts (10 per thread, Hillis-Steele over 256 partials)
    int base = t * 10;
    int loc[10];
    int s = 0;
    if (base < N_) {
#pragma unroll
        for (int i = 0; i < 10; i++) { loc[i] = cnt[base + i]; s += loc[i]; }
    }
    sm[t] = s;
    __syncthreads();
    for (int o = 1; o < 256; o <<= 1) {
        int vv = (t >= o) ? sm[t - o] : 0;
        __syncthreads();
        sm[t] += vv;
        __syncthreads();
    }
    int excl = sm[t] - s;
    if (base < N_) {
        int off = excl;
#pragma unroll
        for (int i = 0; i < 10; i++) {
            g_off[g*(N_+1) + base + i] = off;
            cur[base + i] = off;
            g_dinv[g*N_ + base + i] = rsqrtf((float)loc[i] + 1.0f);
            off += loc[i];
        }
    }
    if (t == 255) g_off[g*(N_+1) + N_] = sm[255];
    __syncthreads();

    // scatter edges into CSR via smem cursors
    for (int i = t; i < E_; i += 256) {
        int2 rc = eg[i];
        int pos = atomicAdd(&cur[rc.y], 1);
        g_rows[(size_t)g*E_ + pos] = rc.x;
    }

    // pool init + grid-barrier reset (for this replay)
    g_pool[g*256 + t] = 0x80000000;
    if (g == 0 && t == 0) { g_bar_cnt = 0; g_bar_gen = 0; }
}

// nop to position the ncu capture slot on k_agg_gemm2pool (capture = 4th launch)
__global__ void k_nop() {}

// ---------------- fused GCN layer 1: embed + aggregate + GEMM(64->128) ----------------
// 50 nodes/block, 128 threads. grid 5000. Edge data staged as packed float4.
#define CAP1 384
__global__ __launch_bounds__(128) void k_agg_gemm1(
        const float* __restrict__ v, const float* __restrict__ W_emb,
        const float* __restrict__ b_emb, const float* __restrict__ W_g1,
        const float* __restrict__ b_g1) {
    __shared__ __align__(16) float As[50*68];   // As[m*68 + k]   13600 B
    __shared__ float Ws[16*128];                //                 8192 B
    __shared__ __align__(16) float4 ed_s[CAP1]; // {v0,v1,v2,nrm}  6144 B
    __shared__ int   off_s[51];
    __shared__ float dnode[50];
    __shared__ float vself[50*3];
    int n0 = blockIdx.x * 50;
    int g = n0 / N_;
    int lnbase = n0 - g * N_;
    int t  = threadIdx.x;

    const float* dv = g_dinv + g*N_;
    const float* vg = v + (size_t)g * N_ * 3;
    if (t < 51) off_s[t] = g_off[g*(N_+1) + lnbase + t];
    if (t < 50) dnode[t] = dv[lnbase + t];
    for (int idx = t; idx < 150; idx += 128) vself[idx] = vg[(size_t)lnbase*3 + idx];
    __syncthreads();
    int e0 = off_s[0];
    int ecnt = off_s[50] - e0;
    const int* rowsg = g_rows + g*E_ + e0;
    for (int i = t; i < ecnt && i < CAP1; i += 128) {
        int r = rowsg[i];
        const float* vp = vg + (size_t)r*3;
        ed_s[i] = make_float4(vp[0], vp[1], vp[2], dv[r]);
    }
    __syncthreads();

    // stage 1: As[m][c] = (A_hat relu(emb(v)))[n0+m][c]
    {
        int c = t & 63;
        int msub = t >> 6;
        float we0 = __ldg(W_emb + c), we1 = __ldg(W_emb + 64 + c);
        float we2 = __ldg(W_emb + 128 + c), be = __ldg(b_emb + c);
#pragma unroll 1
        for (int p = 0; p < 25; p++) {
            int m = p*2 + msub;
            float di = dnode[m];
            float xv = fmaxf(fmaf(vself[m*3+2], we2,
                         fmaf(vself[m*3+1], we1, fmaf(vself[m*3], we0, be))), 0.f);
            float acc = di * di * xv;
            int o0 = off_s[m] - e0, o1 = off_s[m+1] - e0;
            for (int e = o0; e < o1; e++) {
                float4 ed;
                if (e < CAP1) ed = ed_s[e];
                else {
                    int r = rowsg[e];
                    const float* vq = vg + (size_t)r*3;
                    ed = make_float4(vq[0], vq[1], vq[2], dv[r]);
                }
                float xn = fmaxf(fmaf(ed.z, we2, fmaf(ed.y, we1, fmaf(ed.x, we0, be))), 0.f);
                acc = fmaf(di * ed.w, xn, acc);
            }
            As[m*68 + c] = acc;
        }
    }
    __syncthreads();

    // stage 2: h1 = leaky(As @ W_g1 + b), out channel = t, W chunked 16 k-rows
    float2 acc[25];
#pragma unroll
    for (int j = 0; j < 25; j++) acc[j] = make_float2(0.f, 0.f);
    for (int kc = 0; kc < 4; kc++) {
#pragma unroll
        for (int idx = t; idx < 16*128; idx += 128) Ws[idx] = W_g1[kc*16*128 + idx];
        __syncthreads();
#pragma unroll
        for (int kk = 0; kk < 16; kk += 4) {
            float w0 = Ws[(kk  )*128 + t];
            float w1 = Ws[(kk+1)*128 + t];
            float w2 = Ws[(kk+2)*128 + t];
            float w3 = Ws[(kk+3)*128 + t];
            int kb = kc*16 + kk;
#pragma unroll
            for (int mp = 0; mp < 25; mp++) {
                float4 a0 = *(const float4*)(As + (2*mp  )*68 + kb);
                float4 a1 = *(const float4*)(As + (2*mp+1)*68 + kb);
                acc[mp] = ffma2(make_float2(a0.x, a1.x), make_float2(w0, w0), acc[mp]);
                acc[mp] = ffma2(make_float2(a0.y, a1.y), make_float2(w1, w1), acc[mp]);
                acc[mp] = ffma2(make_float2(a0.z, a1.z), make_float2(w2, w2), acc[mp]);
                acc[mp] = ffma2(make_float2(a0.w, a1.w), make_float2(w3, w3), acc[mp]);
            }
        }
        __syncthreads();
    }
    float b = b_g1[t];
#pragma unroll
    for (int mp = 0; mp < 25; mp++) {
        g_h1[(size_t)(n0 + 2*mp  )*128 + t] = leaky(acc[mp].x + b);
        g_h1[(size_t)(n0 + 2*mp+1)*128 + t] = leaky(acc[mp].y + b);
    }
}

// ---------------- fused GCN layer 2: aggregate + GEMM(128->256) + max-pool ----------------
// 50 nodes/block, 256 threads. grid 5000. Edge (row, nrm) staged packed.
#define CAP2 384
__global__ __launch_bounds__(256) void k_agg_gemm2pool(
        const float* __restrict__ W_g2, const float* __restrict__ b_g2) {
    __shared__ __align__(16) float As[50*132];  // 26400 B
    __shared__ float Ws[16*256];                // 16384 B
    __shared__ __align__(8) float2 en_s[CAP2];  // {row_as_float, nrm} 3072 B
    __shared__ int   off_s[51];
    __shared__ float dnode[50];
    int n0 = blockIdx.x * 50;
    int g = n0 / N_;
    int lnbase = n0 - g * N_;
    int t = threadIdx.x;

    const float* dv = g_dinv + g*N_;
    if (t < 51) off_s[t] = g_off[g*(N_+1) + lnbase + t];
    if (t < 50) dnode[t] = dv[lnbase + t];
    __syncthreads();
    int e0 = off_s[0];
    int ecnt = off_s[50] - e0;
    const int* rowsg = g_rows + g*E_ + e0;
    for (int i = t; i < ecnt && i < CAP2; i += 256) {
        int r = rowsg[i];
        en_s[i] = make_float2(__int_as_float(r), dv[r]);
    }
    __syncthreads();

    // stage 1: As[m][c] = (A_hat h1)[n0+m][c]
    {
        int c = t & 127;
        int msub = t >> 7;
        const float* h1g = g_h1 + (size_t)g * N_ * 128;
#pragma unroll 1
        for (int p = 0; p < 25; p++) {
            int m = p*2 + msub;
            float di = dnode[m];
            float acc = di * di * h1g[(size_t)(lnbase+m)*128 + c];
            int o0 = off_s[m] - e0, o1 = off_s[m+1] - e0;
            int e = o0;
            for (; e + 1 < o1; e += 2) {
                float2 p0, p1;
                if (e + 1 < CAP2) { p0 = en_s[e]; p1 = en_s[e+1]; }
                else {
                    int r0 = rowsg[e], r1 = rowsg[e+1];
                    p0 = make_float2(__int_as_float(r0), dv[r0]);
                    p1 = make_float2(__int_as_float(r1), dv[r1]);
                }
                float a0 = h1g[(size_t)__float_as_int(p0.x)*128 + c];
                float a1 = h1g[(size_t)__float_as_int(p1.x)*128 + c];
                acc = fmaf(di * p0.y, a0, acc);
                acc = fmaf(di * p1.y, a1, acc);
            }
            if (e < o1) {
                float2 p0;
                if (e < CAP2) p0 = en_s[e];
                else { int r0 = rowsg[e]; p0 = make_float2(__int_as_float(r0), dv[r0]); }
                acc = fmaf(di * p0.y, h1g[(size_t)__float_as_int(p0.x)*128 + c], acc);
            }
            As[m*132 + c] = acc;
        }
    }
    __syncthreads();

    // stage 2: GEMM 128->256 with k-chunked Ws, fused leaky+bias+max-pool
    float2 acc[25];
#pragma unroll
    for (int j = 0; j < 25; j++) acc[j] = make_float2(0.f, 0.f);
    for (int kc = 0; kc < 8; kc++) {
#pragma unroll
        for (int idx = t; idx < 16*256; idx += 256) Ws[idx] = W_g2[kc*16*256 + idx];
        __syncthreads();
#pragma unroll
        for (int kk = 0; kk < 16; kk += 4) {
            float w0 = Ws[(kk  )*256 + t];
            float w1 = Ws[(kk+1)*256 + t];
            float w2 = Ws[(kk+2)*256 + t];
            float w3 = Ws[(kk+3)*256 + t];
            int kb = kc*16 + kk;
#pragma unroll
            for (int mp = 0; mp < 25; mp++) {
                float4 a0 = *(const float4*)(As + (2*mp  )*132 + kb);
                float4 a1 = *(const float4*)(As + (2*mp+1)*132 + kb);
                acc[mp] = ffma2(make_float2(a0.x, a1.x), make_float2(w0, w0), acc[mp]);
                acc[mp] = ffma2(make_float2(a0.y, a1.y), make_float2(w1, w1), acc[mp]);
                acc[mp] = ffma2(make_float2(a0.z, a1.z), make_float2(w2, w2), acc[mp]);
                acc[mp] = ffma2(make_float2(a0.w, a1.w), make_float2(w3, w3), acc[mp]);
            }
        }
        __syncthreads();
    }
    float b = b_g2[t];
    float m = -1e30f;
#pragma unroll
    for (int mp = 0; mp < 25; mp++) {
        m = fmaxf(m, leaky(acc[mp].x + b));
        m = fmaxf(m, leaky(acc[mp].y + b));
    }
    atomicMax(&g_pool[g*256 + t], fkey(m));
}

// decode pool, FC(256->32, relu) + pe; seeds mu/sigma rows. grid G_, 256 thr.
__global__ void k_fc(const float* __restrict__ W_fc, const float* __restrict__ b_fc,
                     const float* __restrict__ pe, const float* __restrict__ muQ,
                     const float* __restrict__ sigQ) {
    int g = blockIdx.x;
    int t = threadIdx.x;
    __shared__ float ps[256];
    ps[t] = fdec(g_pool[g*256 + t]);
    __syncthreads();
    if (t < 32) {
        float acc = b_fc[t];
        for (int k = 0; k < 256; k++) acc = fmaf(ps[k], W_fc[k*32 + t], acc);
        acc = fmaxf(acc, 0.0f);
        int b = g / 50, s = g - b*50;
        int tk = 2 + s;
        g_xseq[(tk*2 + b)*D_ + t] = acc + pe[tk*D_ + t];
    }
    if (g == 0 && t >= 128 && t < 256) {
        int i = t - 128;
        if (i < 128) {
            int tk = i >> 6;
            int bb = (i >> 5) & 1;
            int d = i & 31;
            g_xseq[(tk*2 + bb)*D_ + d] = (tk == 0 ? muQ[d] : sigQ[d]) + pe[tk*D_ + d];
        }
    }
}

// ---------------- single-kernel transformer (104 resident blocks, grid barrier) ----------------

__device__ __forceinline__ void grid_bar(int target) {
    __syncthreads();
    if (threadIdx.x == 0) {
        __threadfence();
        int v = atomicAdd(&g_bar_cnt, 1);
        if (v + 1 == NB_ * target) {
            g_bar_gen = target;
        } else {
            while (g_bar_gen < target) { }
        }
        __threadfence();
    }
    __syncthreads();
}

__global__ __launch_bounds__(256) void k_transformer(
        const float* __restrict__ in_w, const float* __restrict__ in_b,
        const float* __restrict__ out_w, const float* __restrict__ out_b,
        const float* __restrict__ ln1g, const float* __restrict__ ln1b,
        const float* __restrict__ w1, const float* __restrict__ b1,
        const float* __restrict__ w2, const float* __restrict__ b2,
        const float* __restrict__ ln2g, const float* __restrict__ ln2b,
        float* __restrict__ out) {
    __shared__ float wsq[96*33];             // qkv weights (this layer)
    __shared__ float ow[32*33];              // out-proj weights
    __shared__ __align__(16) float xv[32];   // current token vector
    __shared__ float at[32];                 // attention output
    __shared__ __align__(16) float xs[32];   // post-LN1
    __shared__ float gs[1024];
    __shared__ float ffo[32];
    int tau = blockIdx.x;
    int t = threadIdx.x;
    int wid = t >> 5, lane = t & 31;
    int b = tau & 1;

    if (t < 32) xv[t] = g_xseq[tau*32 + t];

    for (int l = 0; l < 4; l++) {
        for (int idx = t; idx < 96*32; idx += 256)
            wsq[(idx >> 5)*33 + (idx & 31)] = in_w[l*96*32 + idx];
        for (int idx = t; idx < 1024; idx += 256)
            ow[(idx >> 5)*33 + (idx & 31)] = out_w[l*1024 + idx];
        __syncthreads();

        float* qk = g_qkvbuf[l & 1];
        if (t < 96) {
            float acc = in_b[l*96 + t];
#pragma unroll
            for (int d = 0; d < 32; d++) acc = fmaf(xv[d], wsq[t*33 + d], acc);
            qk[tau*96 + t] = acc;
        }
        grid_bar(l + 1);   // all tokens' qkv visible

        // attention: warp h handles head h; lanes cover s = lane, lane+32
        if (wid < 4) {
            int h = wid;
            float4 qa = *(const float4*)(qk + tau*96 + h*8);
            float4 qb = *(const float4*)(qk + tau*96 + h*8 + 4);
            int s0 = lane, s1 = lane + 32;
            const float* k0 = qk + (s0*2 + b)*96 + 32 + h*8;
            float4 ka = *(const float4*)(k0);
            float4 kb = *(const float4*)(k0 + 4);
            float sc0 = (qa.x*ka.x + qa.y*ka.y + qa.z*ka.z + qa.w*ka.w +
                         qb.x*kb.x + qb.y*kb.y + qb.z*kb.z + qb.w*kb.w) * 0.35355339059327373f;
            const float* v0p = qk + (s0*2 + b)*96 + 64 + h*8;
            float4 va = *(const float4*)(v0p);
            float4 vb = *(const float4*)(v0p + 4);
            float sc1 = -1e30f;
            float4 wa = make_float4(0.f,0.f,0.f,0.f), wb = wa;
            if (s1 < T_) {
                const float* k1 = qk + (s1*2 + b)*96 + 32 + h*8;
                float4 kc = *(const float4*)(k1);
                float4 kd = *(const float4*)(k1 + 4);
                sc1 = (qa.x*kc.x + qa.y*kc.y + qa.z*kc.z + qa.w*kc.w +
                       qb.x*kd.x + qb.y*kd.y + qb.z*kd.z + qb.w*kd.w) * 0.35355339059327373f;
                const float* v1p = qk + (s1*2 + b)*96 + 64 + h*8;
                wa = *(const float4*)(v1p);
                wb = *(const float4*)(v1p + 4);
            }
            float mx = warp_max(fmaxf(sc0, sc1));
            float p0 = expf(sc0 - mx);
            float p1 = (s1 < T_) ? expf(sc1 - mx) : 0.f;
            float sum = warp_sum(p0 + p1);
            float o[8];
            o[0] = p0*va.x + p1*wa.x;  o[1] = p0*va.y + p1*wa.y;
            o[2] = p0*va.z + p1*wa.z;  o[3] = p0*va.w + p1*wa.w;
            o[4] = p0*vb.x + p1*wb.x;  o[5] = p0*vb.y + p1*wb.y;
            o[6] = p0*vb.z + p1*wb.z;  o[7] = p0*vb.w + p1*wb.w;
#pragma unroll
            for (int e = 0; e < 8; e++) o[e] = warp_sum(o[e]);
            if (lane == 0) {
                float inv = 1.0f / sum;
#pragma unroll
                for (int e = 0; e < 8; e++) at[h*8 + e] = o[e] * inv;
            }
        }
        __syncthreads();

        // out-proj + residual + LN1
        if (t < 32) {
            float o = out_b[l*32 + t];
#pragma unroll
            for (int c = 0; c < 32; c++) o = fmaf(at[c], ow[t*33 + c], o);
            float val = xv[t] + o;
            float mean = warp_sum(val) * (1.0f/32.0f);
            float dvv = val - mean;
            float var = warp_sum(dvv*dvv) * (1.0f/32.0f);
            xs[t] = dvv * rsqrtf(var + 1e-5f) * ln1g[l*32 + t] + ln1b[l*32 + t];
        }
        __syncthreads();

        // FF: 32 -> 1024 (gelu) -> 32
        float4 xr[8];
#pragma unroll
        for (int i = 0; i < 8; i++) xr[i] = *(const float4*)(xs + i*4);
        const float* w1l = w1 + (size_t)l*1024*32;
        const float* b1l = b1 + l*1024;
#pragma unroll
        for (int i = 0; i < 4; i++) {
            int f = t*4 + i;
            float acc = b1l[f];
            const float4* wr = (const float4*)(w1l + (size_t)f*32);
#pragma unroll
            for (int d4 = 0; d4 < 8; d4++) {
                float4 w = wr[d4];
                float4 x = xr[d4];
                acc = fmaf(w.x, x.x, acc);
                acc = fmaf(w.y, x.y, acc);
                acc = fmaf(w.z, x.z, acc);
                acc = fmaf(w.w, x.w, acc);
            }
            gs[f] = 0.5f * acc * (1.0f + erff(acc * 0.70710678118654752f));
        }
        __syncthreads();
        const float* w2l = w2 + (size_t)l*32*1024;
#pragma unroll
        for (int pass = 0; pass < 4; pass++) {
            int d = pass*8 + wid;
            const float* wrow = w2l + (size_t)d*1024;
            float p = 0.f;
#pragma unroll 8
            for (int j = 0; j < 32; j++) p = fmaf(gs[j*32 + lane], wrow[j*32 + lane], p);
            p = warp_sum(p);
            if (lane == 0) ffo[d] = p;
        }
        __syncthreads();
        if (t < 32) {
            float val = xs[t] + ffo[t] + b2[l*32 + t];
            float mean = warp_sum(val) * (1.0f/32.0f);
            float dvv = val - mean;
            float var = warp_sum(dvv*dvv) * (1.0f/32.0f);
            xv[t] = dvv * rsqrtf(var + 1e-5f) * ln2g[l*32 + t] + ln2b[l*32 + t];
        }
        __syncthreads();
    }

    // output: [mu(64) | logvar(64) | xseq(3328)]
    if (t < 32) {
        float y = xv[t];
        out[128 + tau*32 + t] = y;
        if (tau < 4) out[tau*32 + t] = y;
    }
}

// ---------------- launch ----------------
extern "C" void kernel_launch(void* const* d_in, const int* in_sizes, int n_in,
                              void* d_out, int out_size) {
    const float* v     = (const float*)d_in[0];
    const int*   edge  = (const int*)d_in[2];
    const float* W_emb = (const float*)d_in[3];
    const float* b_emb = (const float*)d_in[4];
    const float* W_g1  = (const float*)d_in[5];
    const float* b_g1  = (const float*)d_in[6];
    const float* W_g2  = (const float*)d_in[7];
    const float* b_g2  = (const float*)d_in[8];
    const float* W_fc  = (const float*)d_in[9];
    const float* b_fc  = (const float*)d_in[10];
    const float* muQ   = (const float*)d_in[11];
    const float* sigQ  = (const float*)d_in[12];
    const float* pe    = (const float*)d_in[13];
    const float* in_w  = (const float*)d_in[14];
    const float* in_b  = (const float*)d_in[15];
    const float* out_w = (const float*)d_in[16];
    const float* out_b = (const float*)d_in[17];
    const float* ln1g  = (const float*)d_in[18];
    const float* ln1b  = (const float*)d_in[19];
    const float* w1    = (const float*)d_in[20];
    const float* b1    = (const float*)d_in[21];
    const float* w2    = (const float*)d_in[22];
    const float* b2    = (const float*)d_in[23];
    const float* ln2g  = (const float*)d_in[24];
    const float* ln2b  = (const float*)d_in[25];

    k_prep<<<G_, 256>>>(edge);                                   // 0
    k_nop<<<1, 32>>>();                                          // 1
    k_agg_gemm1<<<5000, 128>>>(v, W_emb, b_emb, W_g1, b_g1);     // 2
    k_agg_gemm2pool<<<5000, 256>>>(W_g2, b_g2);                  // 3 <- ncu capture slot
    k_fc<<<G_, 256>>>(W_fc, b_fc, pe, muQ, sigQ);                // 4
    k_transformer<<<NB_, 256>>>(in_w, in_b, out_w, out_b, ln1g, ln1b,
                                w1, b1, w2, b2, ln2g, ln2b, (float*)d_out);  // 5
}

// round 7
// speedup vs baseline: 1.4272x; 1.0736x over previous
#include <cuda_runtime.h>
#include <math.h>
#include <stdint.h>

// ---------------- problem constants ----------------
#define G_  100        // B*S graphs
#define N_  2500       // nodes per graph
#define E_  7500       // edges per graph
#define TOT_NODES 250000
#define TOT_EDGES 750000
#define T_  52         // sequence length (S+2)
#define D_  32         // d_model
#define NB_ 104        // transformer blocks (tokens)

// ---------------- scratch (static, allocation-free) ----------------
__device__ float g_h1[TOT_NODES * 128];       // 128 MB
__device__ float g_dinv[TOT_NODES];
__device__ int   g_off[G_*(N_+1)];
__device__ int   g_rows[TOT_EDGES];
__device__ int   g_pool[G_*256];
__device__ float g_xseq[T_*2*D_];             // [t][b][d]
__device__ float g_qkvbuf[2][NB_*96];
__device__ int   g_bar_cnt;
__device__ volatile int g_bar_gen;

// ---------------- helpers ----------------
__device__ __forceinline__ float2 ffma2(float2 a, float2 b, float2 c) {
    union U { float2 f; unsigned long long u; } ua, ub, uc;
    ua.f = a; ub.f = b; uc.f = c;
    asm("fma.rn.f32x2 %0, %1, %2, %3;" : "=l"(uc.u) : "l"(ua.u), "l"(ub.u), "l"(uc.u));
    return uc.f;
}

__device__ __forceinline__ float warp_sum(float v) {
#pragma unroll
    for (int o = 16; o; o >>= 1) v += __shfl_xor_sync(0xffffffffu, v, o);
    return v;
}
__device__ __forceinline__ float warp_max(float v) {
#pragma unroll
    for (int o = 16; o; o >>= 1) v = fmaxf(v, __shfl_xor_sync(0xffffffffu, v, o));
    return v;
}

__device__ __forceinline__ float leaky(float x) {
    return x >= 0.0f ? x : 0.15f * x;
}

// ordered-int encoding for float atomicMax (monotone in float order)
__device__ __forceinline__ int fkey(float f) {
    int i = __float_as_int(f);
    return i >= 0 ? i : (i ^ 0x7FFFFFFF);
}
__device__ __forceinline__ float fdec(int k) {
    return __int_as_float(k >= 0 ? k : (k ^ 0x7FFFFFFF));
}

// ---------------- fused graph prep: count + scan + dinv + scatter + pool init ----------------
// block = graph. 100 blocks, 256 threads.
__global__ __launch_bounds__(256) void k_prep(const int* __restrict__ edge) {
    __shared__ int cnt[N_];       // 10000 B
    __shared__ int cur[N_];       // 10000 B
    __shared__ int sm[256];
    int g = blockIdx.x;
    int t = threadIdx.x;
    for (int i = t; i < N_; i += 256) cnt[i] = 0;
    __syncthreads();

    const int2* eg = (const int2*)edge + (size_t)g * E_;
    for (int i = t; i < E_; i += 256) {
        int2 rc = eg[i];
        atomicAdd(&cnt[rc.y], 1);
    }
    __syncthreads();

    int base = t * 10;
    int loc[10];
    int s = 0;
    if (base < N_) {
#pragma unroll
        for (int i = 0; i < 10; i++) { loc[i] = cnt[base + i]; s += loc[i]; }
    }
    sm[t] = s;
    __syncthreads();
    for (int o = 1; o < 256; o <<= 1) {
        int vv = (t >= o) ? sm[t - o] : 0;
        __syncthreads();
        sm[t] += vv;
        __syncthreads();
    }
    int excl = sm[t] - s;
    if (base < N_) {
        int off = excl;
#pragma unroll
        for (int i = 0; i < 10; i++) {
            g_off[g*(N_+1) + base + i] = off;
            cur[base + i] = off;
            g_dinv[g*N_ + base + i] = rsqrtf((float)loc[i] + 1.0f);
            off += loc[i];
        }
    }
    if (t == 255) g_off[g*(N_+1) + N_] = sm[255];
    __syncthreads();

    for (int i = t; i < E_; i += 256) {
        int2 rc = eg[i];
        int pos = atomicAdd(&cur[rc.y], 1);
        g_rows[(size_t)g*E_ + pos] = rc.x;
    }

    g_pool[g*256 + t] = 0x80000000;
    if (g == 0 && t == 0) { g_bar_cnt = 0; g_bar_gen = 0; }
}

// nop to position the ncu capture slot on k_agg_gemm2pool (capture = 4th launch)
__global__ void k_nop() {}

// ---------------- fused GCN layer 1: embed + aggregate + GEMM(64->128) ----------------
// 50 nodes/block, 128 threads. grid 5000. As stored k-major [64][56] so FFMA2
// operand pairs come straight out of LDS.128 quads (no packing MOVs).
#define CAP1 320
__global__ __launch_bounds__(128) void k_agg_gemm1(
        const float* __restrict__ v, const float* __restrict__ W_emb,
        const float* __restrict__ b_emb, const float* __restrict__ W_g1,
        const float* __restrict__ b_g1) {
    __shared__ __align__(16) float As[64*56];   // k-major: As[k*56 + m]  14336 B
    __shared__ float Ws[16*128];                //                         8192 B
    __shared__ __align__(16) float4 ed_s[CAP1]; // {v0,v1,v2,nrm}          5120 B
    __shared__ int   off_s[51];
    __shared__ float dnode[50];
    __shared__ float vself[50*3];
    int n0 = blockIdx.x * 50;
    int g = n0 / N_;
    int lnbase = n0 - g * N_;
    int t  = threadIdx.x;

    const float* dv = g_dinv + g*N_;
    const float* vg = v + (size_t)g * N_ * 3;
    if (t < 51) off_s[t] = g_off[g*(N_+1) + lnbase + t];
    if (t < 50) dnode[t] = dv[lnbase + t];
    for (int idx = t; idx < 150; idx += 128) vself[idx] = vg[(size_t)lnbase*3 + idx];
    __syncthreads();
    int e0 = off_s[0];
    int ecnt = off_s[50] - e0;
    const int* rowsg = g_rows + g*E_ + e0;
    for (int i = t; i < ecnt && i < CAP1; i += 128) {
        int r = rowsg[i];
        const float* vp = vg + (size_t)r*3;
        ed_s[i] = make_float4(vp[0], vp[1], vp[2], dv[r]);
    }
    __syncthreads();

    // stage 1: As[c][m] = (A_hat relu(emb(v)))[n0+m][c],  c = k-dim of GEMM
    {
        int c = t & 63;
        int msub = t >> 6;
        float we0 = __ldg(W_emb + c), we1 = __ldg(W_emb + 64 + c);
        float we2 = __ldg(W_emb + 128 + c), be = __ldg(b_emb + c);
#pragma unroll 1
        for (int p = 0; p < 25; p++) {
            int m = p*2 + msub;
            float di = dnode[m];
            float xv = fmaxf(fmaf(vself[m*3+2], we2,
                         fmaf(vself[m*3+1], we1, fmaf(vself[m*3], we0, be))), 0.f);
            float acc = di * di * xv;
            int o0 = off_s[m] - e0, o1 = off_s[m+1] - e0;
            for (int e = o0; e < o1; e++) {
                float4 ed;
                if (e < CAP1) ed = ed_s[e];
                else {
                    int r = rowsg[e];
                    const float* vq = vg + (size_t)r*3;
                    ed = make_float4(vq[0], vq[1], vq[2], dv[r]);
                }
                float xn = fmaxf(fmaf(ed.z, we2, fmaf(ed.y, we1, fmaf(ed.x, we0, be))), 0.f);
                acc = fmaf(di * ed.w, xn, acc);
            }
            As[c*56 + m] = acc;
        }
    }
    __syncthreads();

    // stage 2: h1 = leaky(As^T @ W_g1 + b), out channel = t; 4 chunks of 16 k
    float2 acc[25];
#pragma unroll
    for (int j = 0; j < 25; j++) acc[j] = make_float2(0.f, 0.f);
    for (int kc = 0; kc < 4; kc++) {
#pragma unroll
        for (int i = 0; i < 16; i++) Ws[i*128 + t] = W_g1[(kc*16 + i)*128 + t];
        __syncthreads();
#pragma unroll
        for (int kk = 0; kk < 16; kk++) {
            float w = Ws[kk*128 + t];
            float2 wp = make_float2(w, w);
            const float4* arow = (const float4*)(As + (kc*16 + kk)*56);
#pragma unroll
            for (int q = 0; q < 12; q++) {
                float4 a = arow[q];
                acc[2*q]   = ffma2(make_float2(a.x, a.y), wp, acc[2*q]);
                acc[2*q+1] = ffma2(make_float2(a.z, a.w), wp, acc[2*q+1]);
            }
            float2 a24 = ((const float2*)arow)[24];   // m = 48,49
            acc[24] = ffma2(a24, wp, acc[24]);
        }
        __syncthreads();
    }
    float b = b_g1[t];
#pragma unroll
    for (int mp = 0; mp < 25; mp++) {
        g_h1[(size_t)(n0 + 2*mp  )*128 + t] = leaky(acc[mp].x + b);
        g_h1[(size_t)(n0 + 2*mp+1)*128 + t] = leaky(acc[mp].y + b);
    }
}

// ---------------- fused GCN layer 2: aggregate + GEMM(128->256) + max-pool ----------------
// 50 nodes/block, 256 threads. grid 5000. As k-major [128][56].
#define CAP2 320
__global__ __launch_bounds__(256) void k_agg_gemm2pool(
        const float* __restrict__ W_g2, const float* __restrict__ b_g2) {
    __shared__ __align__(16) float As[128*56];  // k-major: As[k*56 + m]  28672 B
    __shared__ float Ws[8*256];                 //                         8192 B
    __shared__ __align__(8) float2 en_s[CAP2];  // {row_as_float, nrm}     2560 B
    __shared__ int   off_s[51];
    __shared__ float dnode[50];
    int n0 = blockIdx.x * 50;
    int g = n0 / N_;
    int lnbase = n0 - g * N_;
    int t = threadIdx.x;

    const float* dv = g_dinv + g*N_;
    if (t < 51) off_s[t] = g_off[g*(N_+1) + lnbase + t];
    if (t < 50) dnode[t] = dv[lnbase + t];
    __syncthreads();
    int e0 = off_s[0];
    int ecnt = off_s[50] - e0;
    const int* rowsg = g_rows + g*E_ + e0;
    for (int i = t; i < ecnt && i < CAP2; i += 256) {
        int r = rowsg[i];
        en_s[i] = make_float2(__int_as_float(r), dv[r]);
    }
    __syncthreads();

    // stage 1: As[c][m] = (A_hat h1)[n0+m][c]
    {
        int c = t & 127;
        int msub = t >> 7;
        const float* h1g = g_h1 + (size_t)g * N_ * 128;
#pragma unroll 1
        for (int p = 0; p < 25; p++) {
            int m = p*2 + msub;
            float di = dnode[m];
            float acc = di * di * h1g[(size_t)(lnbase+m)*128 + c];
            int o0 = off_s[m] - e0, o1 = off_s[m+1] - e0;
            int e = o0;
            for (; e + 1 < o1; e += 2) {
                float2 p0, p1;
                if (e + 1 < CAP2) { p0 = en_s[e]; p1 = en_s[e+1]; }
                else {
                    int r0 = rowsg[e], r1 = rowsg[e+1];
                    p0 = make_float2(__int_as_float(r0), dv[r0]);
                    p1 = make_float2(__int_as_float(r1), dv[r1]);
                }
                float a0 = h1g[(size_t)__float_as_int(p0.x)*128 + c];
                float a1 = h1g[(size_t)__float_as_int(p1.x)*128 + c];
                acc = fmaf(di * p0.y, a0, acc);
                acc = fmaf(di * p1.y, a1, acc);
            }
            if (e < o1) {
                float2 p0;
                if (e < CAP2) p0 = en_s[e];
                else { int r0 = rowsg[e]; p0 = make_float2(__int_as_float(r0), dv[r0]); }
                acc = fmaf(di * p0.y, h1g[(size_t)__float_as_int(p0.x)*128 + c], acc);
            }
            As[c*56 + m] = acc;
        }
    }
    __syncthreads();

    // stage 2: GEMM 128->256 (16 chunks of 8 k), fused leaky+bias+max-pool
    float2 acc[25];
#pragma unroll
    for (int j = 0; j < 25; j++) acc[j] = make_float2(0.f, 0.f);
    for (int kc = 0; kc < 16; kc++) {
#pragma unroll
        for (int i = 0; i < 8; i++) Ws[i*256 + t] = W_g2[(kc*8 + i)*256 + t];
        __syncthreads();
#pragma unroll
        for (int kk = 0; kk < 8; kk++) {
            float w = Ws[kk*256 + t];
            float2 wp = make_float2(w, w);
            const float4* arow = (const float4*)(As + (kc*8 + kk)*56);
#pragma unroll
            for (int q = 0; q < 12; q++) {
                float4 a = arow[q];
                acc[2*q]   = ffma2(make_float2(a.x, a.y), wp, acc[2*q]);
                acc[2*q+1] = ffma2(make_float2(a.z, a.w), wp, acc[2*q+1]);
            }
            float2 a24 = ((const float2*)arow)[24];   // m = 48,49
            acc[24] = ffma2(a24, wp, acc[24]);
        }
        __syncthreads();
    }
    float b = b_g2[t];
    float m = -1e30f;
#pragma unroll
    for (int mp = 0; mp < 25; mp++) {
        m = fmaxf(m, leaky(acc[mp].x + b));
        m = fmaxf(m, leaky(acc[mp].y + b));
    }
    atomicMax(&g_pool[g*256 + t], fkey(m));
}

// decode pool, FC(256->32, relu) + pe; seeds mu/sigma rows. grid G_, 256 thr.
__global__ void k_fc(const float* __restrict__ W_fc, const float* __restrict__ b_fc,
                     const float* __restrict__ pe, const float* __restrict__ muQ,
                     const float* __restrict__ sigQ) {
    int g = blockIdx.x;
    int t = threadIdx.x;
    __shared__ float ps[256];
    ps[t] = fdec(g_pool[g*256 + t]);
    __syncthreads();
    if (t < 32) {
        float acc = b_fc[t];
        for (int k = 0; k < 256; k++) acc = fmaf(ps[k], W_fc[k*32 + t], acc);
        acc = fmaxf(acc, 0.0f);
        int b = g / 50, s = g - b*50;
        int tk = 2 + s;
        g_xseq[(tk*2 + b)*D_ + t] = acc + pe[tk*D_ + t];
    }
    if (g == 0 && t >= 128 && t < 256) {
        int i = t - 128;
        if (i < 128) {
            int tk = i >> 6;
            int bb = (i >> 5) & 1;
            int d = i & 31;
            g_xseq[(tk*2 + bb)*D_ + d] = (tk == 0 ? muQ[d] : sigQ[d]) + pe[tk*D_ + d];
        }
    }
}

// ---------------- single-kernel transformer (104 resident blocks, grid barrier) ----------------

__device__ __forceinline__ void grid_bar(int target) {
    __syncthreads();
    if (threadIdx.x == 0) {
        __threadfence();
        int v = atomicAdd(&g_bar_cnt, 1);
        if (v + 1 == NB_ * target) {
            g_bar_gen = target;
        } else {
            while (g_bar_gen < target) { }
        }
        __threadfence();
    }
    __syncthreads();
}

__global__ __launch_bounds__(256) void k_transformer(
        const float* __restrict__ in_w, const float* __restrict__ in_b,
        const float* __restrict__ out_w, const float* __restrict__ out_b,
        const float* __restrict__ ln1g, const float* __restrict__ ln1b,
        const float* __restrict__ w1, const float* __restrict__ b1,
        const float* __restrict__ w2, const float* __restrict__ b2,
        const float* __restrict__ ln2g, const float* __restrict__ ln2b,
        float* __restrict__ out) {
    __shared__ float wsq[96*33];             // qkv weights (this layer)
    __shared__ float ow[32*33];              // out-proj weights
    __shared__ __align__(16) float xv[32];   // current token vector
    __shared__ float at[32];                 // attention output
    __shared__ __align__(16) float xs[32];   // post-LN1
    __shared__ float gs[1024];
    __shared__ float ffo[32];
    int tau = blockIdx.x;
    int t = threadIdx.x;
    int wid = t >> 5, lane = t & 31;
    int b = tau & 1;

    if (t < 32) xv[t] = g_xseq[tau*32 + t];

    for (int l = 0; l < 4; l++) {
        for (int idx = t; idx < 96*32; idx += 256)
            wsq[(idx >> 5)*33 + (idx & 31)] = in_w[l*96*32 + idx];
        for (int idx = t; idx < 1024; idx += 256)
            ow[(idx >> 5)*33 + (idx & 31)] = out_w[l*1024 + idx];
        __syncthreads();

        float* qk = g_qkvbuf[l & 1];
        if (t < 96) {
            float acc = in_b[l*96 + t];
#pragma unroll
            for (int d = 0; d < 32; d++) acc = fmaf(xv[d], wsq[t*33 + d], acc);
            qk[tau*96 + t] = acc;
        }
        grid_bar(l + 1);   // all tokens' qkv visible

        // attention: warp h handles head h; lanes cover s = lane, lane+32
        if (wid < 4) {
            int h = wid;
            float4 qa = *(const float4*)(qk + tau*96 + h*8);
            float4 qb = *(const float4*)(qk + tau*96 + h*8 + 4);
            int s0 = lane, s1 = lane + 32;
            const float* k0 = qk + (s0*2 + b)*96 + 32 + h*8;
            float4 ka = *(const float4*)(k0);
            float4 kb = *(const float4*)(k0 + 4);
            float sc0 = (qa.x*ka.x + qa.y*ka.y + qa.z*ka.z + qa.w*ka.w +
                         qb.x*kb.x + qb.y*kb.y + qb.z*kb.z + qb.w*kb.w) * 0.35355339059327373f;
            const float* v0p = qk + (s0*2 + b)*96 + 64 + h*8;
            float4 va = *(const float4*)(v0p);
            float4 vb = *(const float4*)(v0p + 4);
            float sc1 = -1e30f;
            float4 wa = make_float4(0.f,0.f,0.f,0.f), wb = wa;
            if (s1 < T_) {
                const float* k1 = qk + (s1*2 + b)*96 + 32 + h*8;
                float4 kc = *(const float4*)(k1);
                float4 kd = *(const float4*)(k1 + 4);
                sc1 = (qa.x*kc.x + qa.y*kc.y + qa.z*kc.z + qa.w*kc.w +
                       qb.x*kd.x + qb.y*kd.y + qb.z*kd.z + qb.w*kd.w) * 0.35355339059327373f;
                const float* v1p = qk + (s1*2 + b)*96 + 64 + h*8;
                wa = *(const float4*)(v1p);
                wb = *(const float4*)(v1p + 4);
            }
            float mx = warp_max(fmaxf(sc0, sc1));
            float p0 = expf(sc0 - mx);
            float p1 = (s1 < T_) ? expf(sc1 - mx) : 0.f;
            float sum = warp_sum(p0 + p1);
            float o[8];
            o[0] = p0*va.x + p1*wa.x;  o[1] = p0*va.y + p1*wa.y;
            o[2] = p0*va.z + p1*wa.z;  o[3] = p0*va.w + p1*wa.w;
            o[4] = p0*vb.x + p1*wb.x;  o[5] = p0*vb.y + p1*wb.y;
            o[6] = p0*vb.z + p1*wb.z;  o[7] = p0*vb.w + p1*wb.w;
#pragma unroll
            for (int e = 0; e < 8; e++) o[e] = warp_sum(o[e]);
            if (lane == 0) {
                float inv = 1.0f / sum;
#pragma unroll
                for (int e = 0; e < 8; e++) at[h*8 + e] = o[e] * inv;
            }
        }
        __syncthreads();

        // out-proj + residual + LN1
        if (t < 32) {
            float o = out_b[l*32 + t];
#pragma unroll
            for (int c = 0; c < 32; c++) o = fmaf(at[c], ow[t*33 + c], o);
            float val = xv[t] + o;
            float mean = warp_sum(val) * (1.0f/32.0f);
            float dvv = val - mean;
            float var = warp_sum(dvv*dvv) * (1.0f/32.0f);
            xs[t] = dvv * rsqrtf(var + 1e-5f) * ln1g[l*32 + t] + ln1b[l*32 + t];
        }
        __syncthreads();

        // FF: 32 -> 1024 (gelu) -> 32
        float4 xr[8];
#pragma unroll
        for (int i = 0; i < 8; i++) xr[i] = *(const float4*)(xs + i*4);
        const float* w1l = w1 + (size_t)l*1024*32;
        const float* b1l = b1 + l*1024;
#pragma unroll
        for (int i = 0; i < 4; i++) {
            int f = t*4 + i;
            float acc = b1l[f];
            const float4* wr = (const float4*)(w1l + (size_t)f*32);
#pragma unroll
            for (int d4 = 0; d4 < 8; d4++) {
                float4 w = wr[d4];
                float4 x = xr[d4];
                acc = fmaf(w.x, x.x, acc);
                acc = fmaf(w.y, x.y, acc);
                acc = fmaf(w.z, x.z, acc);
                acc = fmaf(w.w, x.w, acc);
            }
            gs[f] = 0.5f * acc * (1.0f + erff(acc * 0.70710678118654752f));
        }
        __syncthreads();
        const float* w2l = w2 + (size_t)l*32*1024;
#pragma unroll
        for (int pass = 0; pass < 4; pass++) {
            int d = pass*8 + wid;
            const float* wrow = w2l + (size_t)d*1024;
            float p = 0.f;
#pragma unroll 8
            for (int j = 0; j < 32; j++) p = fmaf(gs[j*32 + lane], wrow[j*32 + lane], p);
            p = warp_sum(p);
            if (lane == 0) ffo[d] = p;
        }
        __syncthreads();
        if (t < 32) {
            float val = xs[t] + ffo[t] + b2[l*32 + t];
            float mean = warp_sum(val) * (1.0f/32.0f);
            float dvv = val - mean;
            float var = warp_sum(dvv*dvv) * (1.0f/32.0f);
            xv[t] = dvv * rsqrtf(var + 1e-5f) * ln2g[l*32 + t] + ln2b[l*32 + t];
        }
        __syncthreads();
    }

    // output: [mu(64) | logvar(64) | xseq(3328)]
    if (t < 32) {
        float y = xv[t];
        out[128 + tau*32 + t] = y;
        if (tau < 4) out[tau*32 + t] = y;
    }
}

// ---------------- launch ----------------
extern "C" void kernel_launch(void* const* d_in, const int* in_sizes, int n_in,
                              void* d_out, int out_size) {
    const float* v     = (const float*)d_in[0];
    const int*   edge  = (const int*)d_in[2];
    const float* W_emb = (const float*)d_in[3];
    const float* b_emb = (const float*)d_in[4];
    const float* W_g1  = (const float*)d_in[5];
    const float* b_g1  = (const float*)d_in[6];
    const float* W_g2  = (const float*)d_in[7];
    const float* b_g2  = (const float*)d_in[8];
    const float* W_fc  = (const float*)d_in[9];
    const float* b_fc  = (const float*)d_in[10];
    const float* muQ   = (const float*)d_in[11];
    const float* sigQ  = (const float*)d_in[12];
    const float* pe    = (const float*)d_in[13];
    const float* in_w  = (const float*)d_in[14];
    const float* in_b  = (const float*)d_in[15];
    const float* out_w = (const float*)d_in[16];
    const float* out_b = (const float*)d_in[17];
    const float* ln1g  = (const float*)d_in[18];
    const float* ln1b  = (const float*)d_in[19];
    const float* w1    = (const float*)d_in[20];
    const float* b1    = (const float*)d_in[21];
    const float* w2    = (const float*)d_in[22];
    const float* b2    = (const float*)d_in[23];
    const float* ln2g  = (const float*)d_in[24];
    const float* ln2b  = (const float*)d_in[25];

    k_prep<<<G_, 256>>>(edge);                                   // 0
    k_nop<<<1, 32>>>();                                          // 1
    k_agg_gemm1<<<5000, 128>>>(v, W_emb, b_emb, W_g1, b_g1);     // 2
    k_agg_gemm2pool<<<5000, 256>>>(W_g2, b_g2);                  // 3 <- ncu capture slot
    k_fc<<<G_, 256>>>(W_fc, b_fc, pe, muQ, sigQ);                // 4
    k_transformer<<<NB_, 256>>>(in_w, in_b, out_w, out_b, ln1g, ln1b,
                                w1, b1, w2, b2, ln2g, ln2b, (float*)d_out);  // 5
}

// round 8
// speedup vs baseline: 1.6745x; 1.1733x over previous
#include <cuda_runtime.h>
#include <math.h>
#include <stdint.h>

// ---------------- problem constants ----------------
#define G_  100        // B*S graphs
#define N_  2500       // nodes per graph
#define E_  7500       // edges per graph
#define TOT_NODES 250000
#define TOT_EDGES 750000
#define T_  52         // sequence length (S+2)
#define D_  32         // d_model
#define NB_ 104        // transformer blocks (tokens)

// ---------------- scratch (static, allocation-free) ----------------
__device__ float g_h1[TOT_NODES * 128];       // 128 MB
__device__ float g_dinv[TOT_NODES];
__device__ int   g_off[G_*(N_+1)];
__device__ int   g_rows[TOT_EDGES];
__device__ int   g_pool[G_*256];
__device__ float g_xseq[T_*2*D_];             // [t][b][d]
__device__ float g_qkvbuf[2][NB_*96];
__device__ int   g_bar_cnt;
__device__ volatile int g_bar_gen;

// ---------------- helpers ----------------
__device__ __forceinline__ float2 ffma2(float2 a, float2 b, float2 c) {
    union U { float2 f; unsigned long long u; } ua, ub, uc;
    ua.f = a; ub.f = b; uc.f = c;
    asm("fma.rn.f32x2 %0, %1, %2, %3;" : "=l"(uc.u) : "l"(ua.u), "l"(ub.u), "l"(uc.u));
    return uc.f;
}

__device__ __forceinline__ float warp_sum(float v) {
#pragma unroll
    for (int o = 16; o; o >>= 1) v += __shfl_xor_sync(0xffffffffu, v, o);
    return v;
}
__device__ __forceinline__ float warp_max(float v) {
#pragma unroll
    for (int o = 16; o; o >>= 1) v = fmaxf(v, __shfl_xor_sync(0xffffffffu, v, o));
    return v;
}

__device__ __forceinline__ float leaky(float x) {
    return x >= 0.0f ? x : 0.15f * x;
}

// ordered-int encoding for float atomicMax (monotone in float order)
__device__ __forceinline__ int fkey(float f) {
    int i = __float_as_int(f);
    return i >= 0 ? i : (i ^ 0x7FFFFFFF);
}
__device__ __forceinline__ float fdec(int k) {
    return __int_as_float(k >= 0 ? k : (k ^ 0x7FFFFFFF));
}

// ---------------- fused graph prep ----------------
__global__ __launch_bounds__(256) void k_prep(const int* __restrict__ edge) {
    __shared__ int cnt[N_];
    __shared__ int cur[N_];
    __shared__ int sm[256];
    int g = blockIdx.x;
    int t = threadIdx.x;
    for (int i = t; i < N_; i += 256) cnt[i] = 0;
    __syncthreads();

    const int2* eg = (const int2*)edge + (size_t)g * E_;
    for (int i = t; i < E_; i += 256) {
        int2 rc = eg[i];
        atomicAdd(&cnt[rc.y], 1);
    }
    __syncthreads();

    int base = t * 10;
    int loc[10];
    int s = 0;
    if (base < N_) {
#pragma unroll
        for (int i = 0; i < 10; i++) { loc[i] = cnt[base + i]; s += loc[i]; }
    }
    sm[t] = s;
    __syncthreads();
    for (int o = 1; o < 256; o <<= 1) {
        int vv = (t >= o) ? sm[t - o] : 0;
        __syncthreads();
        sm[t] += vv;
        __syncthreads();
    }
    int excl = sm[t] - s;
    if (base < N_) {
        int off = excl;
#pragma unroll
        for (int i = 0; i < 10; i++) {
            g_off[g*(N_+1) + base + i] = off;
            cur[base + i] = off;
            g_dinv[g*N_ + base + i] = rsqrtf((float)loc[i] + 1.0f);
            off += loc[i];
        }
    }
    if (t == 255) g_off[g*(N_+1) + N_] = sm[255];
    __syncthreads();

    for (int i = t; i < E_; i += 256) {
        int2 rc = eg[i];
        int pos = atomicAdd(&cur[rc.y], 1);
        g_rows[(size_t)g*E_ + pos] = rc.x;
    }

    g_pool[g*256 + t] = 0x80000000;
    if (g == 0 && t == 0) { g_bar_cnt = 0; g_bar_gen = 0; }
}

// nop to keep ncu capture slot on k_agg_gemm2pool (capture = 4th launch)
__global__ void k_nop() {}

// ---------------- fused GCN layer 1: embed + aggregate + GEMM(64->128) ----------------
// 50 nodes/block, 128 threads. As k-major [64][56]. Stage 2: thread owns a
// channel-quad (c4) and an m-group; W read straight from L2 (no smem, no syncs).
#define CAP1 320
__global__ __launch_bounds__(128) void k_agg_gemm1(
        const float* __restrict__ v, const float* __restrict__ W_emb,
        const float* __restrict__ b_emb, const float* __restrict__ W_g1,
        const float* __restrict__ b_g1) {
    __shared__ __align__(16) float As[64*56];   // k-major: As[k*56 + m]
    __shared__ __align__(16) float4 ed_s[CAP1]; // {v0,v1,v2,nrm}
    __shared__ int   off_s[51];
    __shared__ float dnode[50];
    __shared__ float vself[50*3];
    int n0 = blockIdx.x * 50;
    int g = n0 / N_;
    int lnbase = n0 - g * N_;
    int t  = threadIdx.x;

    const float* dv = g_dinv + g*N_;
    const float* vg = v + (size_t)g * N_ * 3;
    if (t < 51) off_s[t] = g_off[g*(N_+1) + lnbase + t];
    if (t < 50) dnode[t] = dv[lnbase + t];
    for (int idx = t; idx < 150; idx += 128) vself[idx] = vg[(size_t)lnbase*3 + idx];
    __syncthreads();
    int e0 = off_s[0];
    int ecnt = off_s[50] - e0;
    const int* rowsg = g_rows + g*E_ + e0;
    for (int i = t; i < ecnt && i < CAP1; i += 128) {
        int r = rowsg[i];
        const float* vp = vg + (size_t)r*3;
        ed_s[i] = make_float4(vp[0], vp[1], vp[2], dv[r]);
    }
    __syncthreads();

    // stage 1: As[c][m] = (A_hat relu(emb(v)))[n0+m][c]
    {
        int c = t & 63;
        int msub = t >> 6;
        float we0 = __ldg(W_emb + c), we1 = __ldg(W_emb + 64 + c);
        float we2 = __ldg(W_emb + 128 + c), be = __ldg(b_emb + c);
#pragma unroll 1
        for (int p = 0; p < 25; p++) {
            int m = p*2 + msub;
            float di = dnode[m];
            float xv = fmaxf(fmaf(vself[m*3+2], we2,
                         fmaf(vself[m*3+1], we1, fmaf(vself[m*3], we0, be))), 0.f);
            float acc = di * di * xv;
            int o0 = off_s[m] - e0, o1 = off_s[m+1] - e0;
            for (int e = o0; e < o1; e++) {
                float4 ed;
                if (e < CAP1) ed = ed_s[e];
                else {
                    int r = rowsg[e];
                    const float* vq = vg + (size_t)r*3;
                    ed = make_float4(vq[0], vq[1], vq[2], dv[r]);
                }
                float xn = fmaxf(fmaf(ed.z, we2, fmaf(ed.y, we1, fmaf(ed.x, we0, be))), 0.f);
                acc = fmaf(di * ed.w, xn, acc);
            }
            As[c*56 + m] = acc;
        }
    }
    __syncthreads();

    // stage 2: thread = (c4 = 4*(t&31), m-group t>>5 of {12,12,12,14})
    {
        int c4 = (t & 31) * 4;
        int mh = t >> 5;
        int mb = mh * 12;
        bool extra = (mh == 3);
        float2 acc[4][7];
#pragma unroll
        for (int j = 0; j < 4; j++)
#pragma unroll
            for (int q = 0; q < 7; q++) acc[j][q] = make_float2(0.f, 0.f);

        const float* Wp = W_g1 + c4;
#pragma unroll 2
        for (int k = 0; k < 64; k++) {
            float4 wv = __ldg((const float4*)(Wp + k*128));
            const float* arow = As + k*56 + mb;
            float4 a0 = *(const float4*)(arow);
            float4 a1 = *(const float4*)(arow + 4);
            float4 a2 = *(const float4*)(arow + 8);
            float wj[4] = {wv.x, wv.y, wv.z, wv.w};
#pragma unroll
            for (int j = 0; j < 4; j++) {
                float2 wp = make_float2(wj[j], wj[j]);
                acc[j][0] = ffma2(make_float2(a0.x, a0.y), wp, acc[j][0]);
                acc[j][1] = ffma2(make_float2(a0.z, a0.w), wp, acc[j][1]);
                acc[j][2] = ffma2(make_float2(a1.x, a1.y), wp, acc[j][2]);
                acc[j][3] = ffma2(make_float2(a1.z, a1.w), wp, acc[j][3]);
                acc[j][4] = ffma2(make_float2(a2.x, a2.y), wp, acc[j][4]);
                acc[j][5] = ffma2(make_float2(a2.z, a2.w), wp, acc[j][5]);
            }
            if (extra) {
                float2 a3 = *(const float2*)(arow + 12);
#pragma unroll
                for (int j = 0; j < 4; j++)
                    acc[j][6] = ffma2(a3, make_float2(wj[j], wj[j]), acc[j][6]);
            }
        }
        float4 bb = __ldg((const float4*)(b_g1 + c4));
        int pc = extra ? 7 : 6;
        for (int q = 0; q < pc; q++) {
            int m = mb + 2*q;
            float4 lo, hi;
            lo.x = leaky(acc[0][q].x + bb.x); lo.y = leaky(acc[1][q].x + bb.y);
            lo.z = leaky(acc[2][q].x + bb.z); lo.w = leaky(acc[3][q].x + bb.w);
            hi.x = leaky(acc[0][q].y + bb.x); hi.y = leaky(acc[1][q].y + bb.y);
            hi.z = leaky(acc[2][q].y + bb.z); hi.w = leaky(acc[3][q].y + bb.w);
            *(float4*)(g_h1 + (size_t)(n0 + m    )*128 + c4) = lo;
            *(float4*)(g_h1 + (size_t)(n0 + m + 1)*128 + c4) = hi;
        }
    }
}

// ---------------- fused GCN layer 2: aggregate + GEMM(128->256) + max-pool ----------------
// 50 nodes/block, 256 threads. As k-major [128][56]. Stage 2 channel-quad scheme.
#define CAP2 320
__global__ __launch_bounds__(256) void k_agg_gemm2pool(
        const float* __restrict__ W_g2, const float* __restrict__ b_g2) {
    __shared__ __align__(16) float As[128*56];  // 28672 B
    __shared__ __align__(8) float2 en_s[CAP2];  // {row_as_float, nrm}
    __shared__ int   off_s[51];
    __shared__ float dnode[50];
    int n0 = blockIdx.x * 50;
    int g = n0 / N_;
    int lnbase = n0 - g * N_;
    int t = threadIdx.x;

    const float* dv = g_dinv + g*N_;
    if (t < 51) off_s[t] = g_off[g*(N_+1) + lnbase + t];
    if (t < 50) dnode[t] = dv[lnbase + t];
    __syncthreads();
    int e0 = off_s[0];
    int ecnt = off_s[50] - e0;
    const int* rowsg = g_rows + g*E_ + e0;
    for (int i = t; i < ecnt && i < CAP2; i += 256) {
        int r = rowsg[i];
        en_s[i] = make_float2(__int_as_float(r), dv[r]);
    }
    __syncthreads();

    // stage 1: As[c][m] = (A_hat h1)[n0+m][c]
    {
        int c = t & 127;
        int msub = t >> 7;
        const float* h1g = g_h1 + (size_t)g * N_ * 128;
#pragma unroll 1
        for (int p = 0; p < 25; p++) {
            int m = p*2 + msub;
            float di = dnode[m];
            float acc = di * di * h1g[(size_t)(lnbase+m)*128 + c];
            int o0 = off_s[m] - e0, o1 = off_s[m+1] - e0;
            int e = o0;
            for (; e + 1 < o1; e += 2) {
                float2 p0, p1;
                if (e + 1 < CAP2) { p0 = en_s[e]; p1 = en_s[e+1]; }
                else {
                    int r0 = rowsg[e], r1 = rowsg[e+1];
                    p0 = make_float2(__int_as_float(r0), dv[r0]);
                    p1 = make_float2(__int_as_float(r1), dv[r1]);
                }
                float a0 = h1g[(size_t)__float_as_int(p0.x)*128 + c];
                float a1 = h1g[(size_t)__float_as_int(p1.x)*128 + c];
                acc = fmaf(di * p0.y, a0, acc);
                acc = fmaf(di * p1.y, a1, acc);
            }
            if (e < o1) {
                float2 p0;
                if (e < CAP2) p0 = en_s[e];
                else { int r0 = rowsg[e]; p0 = make_float2(__int_as_float(r0), dv[r0]); }
                acc = fmaf(di * p0.y, h1g[(size_t)__float_as_int(p0.x)*128 + c], acc);
            }
            As[c*56 + m] = acc;
        }
    }
    __syncthreads();

    // stage 2: thread = (c4 = 4*(t&63), m-group t>>6 of {12,12,12,14}); fused pool
    {
        int c4 = (t & 63) * 4;
        int mh = t >> 6;
        int mb = mh * 12;
        bool extra = (mh == 3);
        float2 acc[4][7];
#pragma unroll
        for (int j = 0; j < 4; j++)
#pragma unroll
            for (int q = 0; q < 7; q++) acc[j][q] = make_float2(0.f, 0.f);

        const float* Wp = W_g2 + c4;
#pragma unroll 2
        for (int k = 0; k < 128; k++) {
            float4 wv = __ldg((const float4*)(Wp + k*256));
            const float* arow = As + k*56 + mb;
            float4 a0 = *(const float4*)(arow);
            float4 a1 = *(const float4*)(arow + 4);
            float4 a2 = *(const float4*)(arow + 8);
            float wj[4] = {wv.x, wv.y, wv.z, wv.w};
#pragma unroll
            for (int j = 0; j < 4; j++) {
                float2 wp = make_float2(wj[j], wj[j]);
                acc[j][0] = ffma2(make_float2(a0.x, a0.y), wp, acc[j][0]);
                acc[j][1] = ffma2(make_float2(a0.z, a0.w), wp, acc[j][1]);
                acc[j][2] = ffma2(make_float2(a1.x, a1.y), wp, acc[j][2]);
                acc[j][3] = ffma2(make_float2(a1.z, a1.w), wp, acc[j][3]);
                acc[j][4] = ffma2(make_float2(a2.x, a2.y), wp, acc[j][4]);
                acc[j][5] = ffma2(make_float2(a2.z, a2.w), wp, acc[j][5]);
            }
            if (extra) {
                float2 a3 = *(const float2*)(arow + 12);
#pragma unroll
                for (int j = 0; j < 4; j++)
                    acc[j][6] = ffma2(a3, make_float2(wj[j], wj[j]), acc[j][6]);
            }
        }
        float4 bb = __ldg((const float4*)(b_g2 + c4));
        float bj[4] = {bb.x, bb.y, bb.z, bb.w};
#pragma unroll
        for (int j = 0; j < 4; j++) {
            float mx = -1e30f;
#pragma unroll
            for (int q = 0; q < 6; q++) {
                mx = fmaxf(mx, leaky(acc[j][q].x + bj[j]));
                mx = fmaxf(mx, leaky(acc[j][q].y + bj[j]));
            }
            if (extra) {
                mx = fmaxf(mx, leaky(acc[j][6].x + bj[j]));
                mx = fmaxf(mx, leaky(acc[j][6].y + bj[j]));
            }
            atomicMax(&g_pool[g*256 + c4 + j], fkey(mx));
        }
    }
}

// decode pool, FC(256->32, relu) + pe; seeds mu/sigma rows. grid G_, 256 thr.
__global__ void k_fc(const float* __restrict__ W_fc, const float* __restrict__ b_fc,
                     const float* __restrict__ pe, const float* __restrict__ muQ,
                     const float* __restrict__ sigQ) {
    int g = blockIdx.x;
    int t = threadIdx.x;
    __shared__ float ps[256];
    ps[t] = fdec(g_pool[g*256 + t]);
    __syncthreads();
    if (t < 32) {
        float acc = b_fc[t];
        for (int k = 0; k < 256; k++) acc = fmaf(ps[k], W_fc[k*32 + t], acc);
        acc = fmaxf(acc, 0.0f);
        int b = g / 50, s = g - b*50;
        int tk = 2 + s;
        g_xseq[(tk*2 + b)*D_ + t] = acc + pe[tk*D_ + t];
    }
    if (g == 0 && t >= 128 && t < 256) {
        int i = t - 128;
        if (i < 128) {
            int tk = i >> 6;
            int bb = (i >> 5) & 1;
            int d = i & 31;
            g_xseq[(tk*2 + bb)*D_ + d] = (tk == 0 ? muQ[d] : sigQ[d]) + pe[tk*D_ + d];
        }
    }
}

// ---------------- single-kernel transformer (104 resident blocks, grid barrier) ----------------

__device__ __forceinline__ void grid_bar(int target) {
    __syncthreads();
    if (threadIdx.x == 0) {
        __threadfence();
        int v = atomicAdd(&g_bar_cnt, 1);
        if (v + 1 == NB_ * target) {
            g_bar_gen = target;
        } else {
            while (g_bar_gen < target) { }
        }
        __threadfence();
    }
    __syncthreads();
}

__global__ __launch_bounds__(256) void k_transformer(
        const float* __restrict__ in_w, const float* __restrict__ in_b,
        const float* __restrict__ out_w, const float* __restrict__ out_b,
        const float* __restrict__ ln1g, const float* __restrict__ ln1b,
        const float* __restrict__ w1, const float* __restrict__ b1,
        const float* __restrict__ w2, const float* __restrict__ b2,
        const float* __restrict__ ln2g, const float* __restrict__ ln2b,
        float* __restrict__ out) {
    __shared__ float wsq[96*33];
    __shared__ float ow[32*33];
    __shared__ __align__(16) float xv[32];
    __shared__ float at[32];
    __shared__ __align__(16) float xs[32];
    __shared__ float gs[1024];
    __shared__ float ffo[32];
    int tau = blockIdx.x;
    int t = threadIdx.x;
    int wid = t >> 5, lane = t & 31;
    int b = tau & 1;

    if (t < 32) xv[t] = g_xseq[tau*32 + t];

    for (int l = 0; l < 4; l++) {
        for (int idx = t; idx < 96*32; idx += 256)
            wsq[(idx >> 5)*33 + (idx & 31)] = in_w[l*96*32 + idx];
        for (int idx = t; idx < 1024; idx += 256)
            ow[(idx >> 5)*33 + (idx & 31)] = out_w[l*1024 + idx];
        __syncthreads();

        float* qk = g_qkvbuf[l & 1];
        if (t < 96) {
            float acc = in_b[l*96 + t];
#pragma unroll
            for (int d = 0; d < 32; d++) acc = fmaf(xv[d], wsq[t*33 + d], acc);
            qk[tau*96 + t] = acc;
        }
        grid_bar(l + 1);

        if (wid < 4) {
            int h = wid;
            float4 qa = *(const float4*)(qk + tau*96 + h*8);
            float4 qb = *(const float4*)(qk + tau*96 + h*8 + 4);
            int s0 = lane, s1 = lane + 32;
            const float* k0 = qk + (s0*2 + b)*96 + 32 + h*8;
            float4 ka = *(const float4*)(k0);
            float4 kb = *(const float4*)(k0 + 4);
            float sc0 = (qa.x*ka.x + qa.y*ka.y + qa.z*ka.z + qa.w*ka.w +
                         qb.x*kb.x + qb.y*kb.y + qb.z*kb.z + qb.w*kb.w) * 0.35355339059327373f;
            const float* v0p = qk + (s0*2 + b)*96 + 64 + h*8;
            float4 va = *(const float4*)(v0p);
            float4 vb = *(const float4*)(v0p + 4);
            float sc1 = -1e30f;
            float4 wa = make_float4(0.f,0.f,0.f,0.f), wb = wa;
            if (s1 < T_) {
                const float* k1 = qk + (s1*2 + b)*96 + 32 + h*8;
                float4 kc = *(const float4*)(k1);
                float4 kd = *(const float4*)(k1 + 4);
                sc1 = (qa.x*kc.x + qa.y*kc.y + qa.z*kc.z + qa.w*kc.w +
                       qb.x*kd.x + qb.y*kd.y + qb.z*kd.z + qb.w*kd.w) * 0.35355339059327373f;
                const float* v1p = qk + (s1*2 + b)*96 + 64 + h*8;
                wa = *(const float4*)(v1p);
                wb = *(const float4*)(v1p + 4);
            }
            float mx = warp_max(fmaxf(sc0, sc1));
            float p0 = expf(sc0 - mx);
            float p1 = (s1 < T_) ? expf(sc1 - mx) : 0.f;
            float sum = warp_sum(p0 + p1);
            float o[8];
            o[0] = p0*va.x + p1*wa.x;  o[1] = p0*va.y + p1*wa.y;
            o[2] = p0*va.z + p1*wa.z;  o[3] = p0*va.w + p1*wa.w;
            o[4] = p0*vb.x + p1*wb.x;  o[5] = p0*vb.y + p1*wb.y;
            o[6] = p0*vb.z + p1*wb.z;  o[7] = p0*vb.w + p1*wb.w;
#pragma unroll
            for (int e = 0; e < 8; e++) o[e] = warp_sum(o[e]);
            if (lane == 0) {
                float inv = 1.0f / sum;
#pragma unroll
                for (int e = 0; e < 8; e++) at[h*8 + e] = o[e] * inv;
            }
        }
        __syncthreads();

        if (t < 32) {
            float o = out_b[l*32 + t];
#pragma unroll
            for (int c = 0; c < 32; c++) o = fmaf(at[c], ow[t*33 + c], o);
            float val = xv[t] + o;
            float mean = warp_sum(val) * (1.0f/32.0f);
            float dvv = val - mean;
            float var = warp_sum(dvv*dvv) * (1.0f/32.0f);
            xs[t] = dvv * rsqrtf(var + 1e-5f) * ln1g[l*32 + t] + ln1b[l*32 + t];
        }
        __syncthreads();

        float4 xr[8];
#pragma unroll
        for (int i = 0; i < 8; i++) xr[i] = *(const float4*)(xs + i*4);
        const float* w1l = w1 + (size_t)l*1024*32;
        const float* b1l = b1 + l*1024;
#pragma unroll
        for (int i = 0; i < 4; i++) {
            int f = t*4 + i;
            float acc = b1l[f];
            const float4* wr = (const float4*)(w1l + (size_t)f*32);
#pragma unroll
            for (int d4 = 0; d4 < 8; d4++) {
                float4 w = wr[d4];
                float4 x = xr[d4];
                acc = fmaf(w.x, x.x, acc);
                acc = fmaf(w.y, x.y, acc);
                acc = fmaf(w.z, x.z, acc);
                acc = fmaf(w.w, x.w, acc);
            }
            gs[f] = 0.5f * acc * (1.0f + erff(acc * 0.70710678118654752f));
        }
        __syncthreads();
        const float* w2l = w2 + (size_t)l*32*1024;
#pragma unroll
        for (int pass = 0; pass < 4; pass++) {
            int d = pass*8 + wid;
            const float* wrow = w2l + (size_t)d*1024;
            float p = 0.f;
#pragma unroll 8
            for (int j = 0; j < 32; j++) p = fmaf(gs[j*32 + lane], wrow[j*32 + lane], p);
            p = warp_sum(p);
            if (lane == 0) ffo[d] = p;
        }
        __syncthreads();
        if (t < 32) {
            float val = xs[t] + ffo[t] + b2[l*32 + t];
            float mean = warp_sum(val) * (1.0f/32.0f);
            float dvv = val - mean;
            float var = warp_sum(dvv*dvv) * (1.0f/32.0f);
            xv[t] = dvv * rsqrtf(var + 1e-5f) * ln2g[l*32 + t] + ln2b[l*32 + t];
        }
        __syncthreads();
    }

    if (t < 32) {
        float y = xv[t];
        out[128 + tau*32 + t] = y;
        if (tau < 4) out[tau*32 + t] = y;
    }
}

// ---------------- launch ----------------
extern "C" void kernel_launch(void* const* d_in, const int* in_sizes, int n_in,
                              void* d_out, int out_size) {
    const float* v     = (const float*)d_in[0];
    const int*   edge  = (const int*)d_in[2];
    const float* W_emb = (const float*)d_in[3];
    const float* b_emb = (const float*)d_in[4];
    const float* W_g1  = (const float*)d_in[5];
    const float* b_g1  = (const float*)d_in[6];
    const float* W_g2  = (const float*)d_in[7];
    const float* b_g2  = (const float*)d_in[8];
    const float* W_fc  = (const float*)d_in[9];
    const float* b_fc  = (const float*)d_in[10];
    const float* muQ   = (const float*)d_in[11];
    const float* sigQ  = (const float*)d_in[12];
    const float* pe    = (const float*)d_in[13];
    const float* in_w  = (const float*)d_in[14];
    const float* in_b  = (const float*)d_in[15];
    const float* out_w = (const float*)d_in[16];
    const float* out_b = (const float*)d_in[17];
    const float* ln1g  = (const float*)d_in[18];
    const float* ln1b  = (const float*)d_in[19];
    const float* w1    = (const float*)d_in[20];
    const float* b1    = (const float*)d_in[21];
    const float* w2    = (const float*)d_in[22];
    const float* b2    = (const float*)d_in[23];
    const float* ln2g  = (const float*)d_in[24];
    const float* ln2b  = (const float*)d_in[25];

    k_prep<<<G_, 256>>>(edge);                                   // 0
    k_nop<<<1, 32>>>();                                          // 1
    k_agg_gemm1<<<5000, 128>>>(v, W_emb, b_emb, W_g1, b_g1);     // 2
    k_agg_gemm2pool<<<5000, 256>>>(W_g2, b_g2);                  // 3 <- ncu capture slot
    k_fc<<<G_, 256>>>(W_fc, b_fc, pe, muQ, sigQ);                // 4
    k_transformer<<<NB_, 256>>>(in_w, in_b, out_w, out_b, ln1g, ln1b,
                                w1, b1, w2, b2, ln2g, ln2b, (float*)d_out);  // 5
}

// round 9
// speedup vs baseline: 2.1371x; 1.2763x over previous
#include <cuda_runtime.h>
#include <math.h>
#include <stdint.h>

// ---------------- problem constants ----------------
#define G_  100        // B*S graphs
#define N_  2500       // nodes per graph
#define E_  7500       // edges per graph
#define TOT_NODES 250000
#define TOT_EDGES 750000
#define T_  52         // sequence length (S+2)
#define D_  32         // d_model
#define NB_ 104        // transformer blocks (tokens)

// ---------------- scratch (static, allocation-free) ----------------
__device__ float g_h1[TOT_NODES * 128];       // 128 MB
__device__ float g_h1a[TOT_NODES * 128];      // 128 MB (edge-aggregated h1)
__device__ float g_dinv[TOT_NODES];
__device__ int   g_off[G_*(N_+1)];
__device__ int   g_rows[TOT_EDGES];
__device__ int   g_pool[G_*256];
__device__ float g_xseq[T_*2*D_];             // [t][b][d]
__device__ float g_qkvbuf[2][NB_*96];
__device__ int   g_bar_cnt;
__device__ volatile int g_bar_gen;

// ---------------- helpers ----------------
__device__ __forceinline__ float2 ffma2(float2 a, float2 b, float2 c) {
    union U { float2 f; unsigned long long u; } ua, ub, uc;
    ua.f = a; ub.f = b; uc.f = c;
    asm("fma.rn.f32x2 %0, %1, %2, %3;" : "=l"(uc.u) : "l"(ua.u), "l"(ub.u), "l"(uc.u));
    return uc.f;
}

__device__ __forceinline__ float warp_sum(float v) {
#pragma unroll
    for (int o = 16; o; o >>= 1) v += __shfl_xor_sync(0xffffffffu, v, o);
    return v;
}
__device__ __forceinline__ float warp_max(float v) {
#pragma unroll
    for (int o = 16; o; o >>= 1) v = fmaxf(v, __shfl_xor_sync(0xffffffffu, v, o));
    return v;
}

__device__ __forceinline__ float leaky(float x) {
    return x >= 0.0f ? x : 0.15f * x;
}

// ordered-int encoding for float atomicMax (monotone in float order)
__device__ __forceinline__ int fkey(float f) {
    int i = __float_as_int(f);
    return i >= 0 ? i : (i ^ 0x7FFFFFFF);
}
__device__ __forceinline__ float fdec(int k) {
    return __int_as_float(k >= 0 ? k : (k ^ 0x7FFFFFFF));
}

// ---------------- fused graph prep ----------------
__global__ __launch_bounds__(256) void k_prep(const int* __restrict__ edge) {
    __shared__ int cnt[N_];
    __shared__ int cur[N_];
    __shared__ int sm[256];
    int g = blockIdx.x;
    int t = threadIdx.x;
    for (int i = t; i < N_; i += 256) cnt[i] = 0;
    __syncthreads();

    const int2* eg = (const int2*)edge + (size_t)g * E_;
    for (int i = t; i < E_; i += 256) {
        int2 rc = eg[i];
        atomicAdd(&cnt[rc.y], 1);
    }
    __syncthreads();

    int base = t * 10;
    int loc[10];
    int s = 0;
    if (base < N_) {
#pragma unroll
        for (int i = 0; i < 10; i++) { loc[i] = cnt[base + i]; s += loc[i]; }
    }
    sm[t] = s;
    __syncthreads();
    for (int o = 1; o < 256; o <<= 1) {
        int vv = (t >= o) ? sm[t - o] : 0;
        __syncthreads();
        sm[t] += vv;
        __syncthreads();
    }
    int excl = sm[t] - s;
    if (base < N_) {
        int off = excl;
#pragma unroll
        for (int i = 0; i < 10; i++) {
            g_off[g*(N_+1) + base + i] = off;
            cur[base + i] = off;
            g_dinv[g*N_ + base + i] = rsqrtf((float)loc[i] + 1.0f);
            off += loc[i];
        }
    }
    if (t == 255) g_off[g*(N_+1) + N_] = sm[255];
    __syncthreads();

    for (int i = t; i < E_; i += 256) {
        int2 rc = eg[i];
        int pos = atomicAdd(&cur[rc.y], 1);
        g_rows[(size_t)g*E_ + pos] = rc.x;
    }

    g_pool[g*256 + t] = 0x80000000;
    if (g == 0 && t == 0) { g_bar_cnt = 0; g_bar_gen = 0; }
}

// ---------------- fused GCN layer 1: embed + aggregate + GEMM(64->128) ----------------
// 50 nodes/block, 128 threads. As k-major [64][56]; stage-2 channel-quad.
#define CAP1 320
__global__ __launch_bounds__(128) void k_agg_gemm1(
        const float* __restrict__ v, const float* __restrict__ W_emb,
        const float* __restrict__ b_emb, const float* __restrict__ W_g1,
        const float* __restrict__ b_g1) {
    __shared__ __align__(16) float As[64*56];
    __shared__ __align__(16) float4 ed_s[CAP1];
    __shared__ int   off_s[51];
    __shared__ float dnode[50];
    __shared__ float vself[50*3];
    int n0 = blockIdx.x * 50;
    int g = n0 / N_;
    int lnbase = n0 - g * N_;
    int t  = threadIdx.x;

    const float* dv = g_dinv + g*N_;
    const float* vg = v + (size_t)g * N_ * 3;
    if (t < 51) off_s[t] = g_off[g*(N_+1) + lnbase + t];
    if (t < 50) dnode[t] = dv[lnbase + t];
    for (int idx = t; idx < 150; idx += 128) vself[idx] = vg[(size_t)lnbase*3 + idx];
    __syncthreads();
    int e0 = off_s[0];
    int ecnt = off_s[50] - e0;
    const int* rowsg = g_rows + g*E_ + e0;
    for (int i = t; i < ecnt && i < CAP1; i += 128) {
        int r = rowsg[i];
        const float* vp = vg + (size_t)r*3;
        ed_s[i] = make_float4(vp[0], vp[1], vp[2], dv[r]);
    }
    __syncthreads();

    // stage 1
    {
        int c = t & 63;
        int msub = t >> 6;
        float we0 = __ldg(W_emb + c), we1 = __ldg(W_emb + 64 + c);
        float we2 = __ldg(W_emb + 128 + c), be = __ldg(b_emb + c);
#pragma unroll 1
        for (int p = 0; p < 25; p++) {
            int m = p*2 + msub;
            float di = dnode[m];
            float xv = fmaxf(fmaf(vself[m*3+2], we2,
                         fmaf(vself[m*3+1], we1, fmaf(vself[m*3], we0, be))), 0.f);
            float acc = di * di * xv;
            int o0 = off_s[m] - e0, o1 = off_s[m+1] - e0;
            for (int e = o0; e < o1; e++) {
                float4 ed;
                if (e < CAP1) ed = ed_s[e];
                else {
                    int r = rowsg[e];
                    const float* vq = vg + (size_t)r*3;
                    ed = make_float4(vq[0], vq[1], vq[2], dv[r]);
                }
                float xn = fmaxf(fmaf(ed.z, we2, fmaf(ed.y, we1, fmaf(ed.x, we0, be))), 0.f);
                acc = fmaf(di * ed.w, xn, acc);
            }
            As[c*56 + m] = acc;
        }
    }
    __syncthreads();

    // stage 2: channel-quad GEMM
    {
        int c4 = (t & 31) * 4;
        int mh = t >> 5;
        int mb = mh * 12;
        bool extra = (mh == 3);
        float2 acc[4][7];
#pragma unroll
        for (int j = 0; j < 4; j++)
#pragma unroll
            for (int q = 0; q < 7; q++) acc[j][q] = make_float2(0.f, 0.f);

        const float* Wp = W_g1 + c4;
#pragma unroll 2
        for (int k = 0; k < 64; k++) {
            float4 wv = __ldg((const float4*)(Wp + k*128));
            const float* arow = As + k*56 + mb;
            float4 a0 = *(const float4*)(arow);
            float4 a1 = *(const float4*)(arow + 4);
            float4 a2 = *(const float4*)(arow + 8);
            float wj[4] = {wv.x, wv.y, wv.z, wv.w};
#pragma unroll
            for (int j = 0; j < 4; j++) {
                float2 wp = make_float2(wj[j], wj[j]);
                acc[j][0] = ffma2(make_float2(a0.x, a0.y), wp, acc[j][0]);
                acc[j][1] = ffma2(make_float2(a0.z, a0.w), wp, acc[j][1]);
                acc[j][2] = ffma2(make_float2(a1.x, a1.y), wp, acc[j][2]);
                acc[j][3] = ffma2(make_float2(a1.z, a1.w), wp, acc[j][3]);
                acc[j][4] = ffma2(make_float2(a2.x, a2.y), wp, acc[j][4]);
                acc[j][5] = ffma2(make_float2(a2.z, a2.w), wp, acc[j][5]);
            }
            if (extra) {
                float2 a3 = *(const float2*)(arow + 12);
#pragma unroll
                for (int j = 0; j < 4; j++)
                    acc[j][6] = ffma2(a3, make_float2(wj[j], wj[j]), acc[j][6]);
            }
        }
        float4 bb = __ldg((const float4*)(b_g1 + c4));
        int pc = extra ? 7 : 6;
        for (int q = 0; q < pc; q++) {
            int m = mb + 2*q;
            float4 lo, hi;
            lo.x = leaky(acc[0][q].x + bb.x); lo.y = leaky(acc[1][q].x + bb.y);
            lo.z = leaky(acc[2][q].x + bb.z); lo.w = leaky(acc[3][q].x + bb.w);
            hi.x = leaky(acc[0][q].y + bb.x); hi.y = leaky(acc[1][q].y + bb.y);
            hi.z = leaky(acc[2][q].y + bb.z); hi.w = leaky(acc[3][q].y + bb.w);
            *(float4*)(g_h1 + (size_t)(n0 + m    )*128 + c4) = lo;
            *(float4*)(g_h1 + (size_t)(n0 + m + 1)*128 + c4) = hi;
        }
    }
}

// ---------------- standalone layer-2 aggregation (edge-only, prefetch pipeline) ----------------
// 50 nodes/block, 256 threads (128 ch x 2 node-halves). Writes g_h1a = sum over
// edges of dv[row]*h1[row]; self term folded into k_gemm2pool. Depth-4 prefetch.
#define CAPA 320
__global__ __launch_bounds__(256) void k_agg128() {
    __shared__ __align__(8) float2 en_s[CAPA];  // {row_as_float, dv[row]}
    __shared__ int   off_s[51];
    __shared__ float dnode[50];
    int n0 = blockIdx.x * 50;
    int g = n0 / N_;
    int lnbase = n0 - g * N_;
    int t = threadIdx.x;

    const float* dv = g_dinv + g*N_;
    if (t < 51) off_s[t] = g_off[g*(N_+1) + lnbase + t];
    if (t < 50) dnode[t] = dv[lnbase + t];
    __syncthreads();
    int e0 = off_s[0];
    int ecnt = off_s[50] - e0;
    const int* rowsg = g_rows + g*E_ + e0;
    for (int i = t; i < ecnt && i < CAPA; i += 256) {
        int r = rowsg[i];
        en_s[i] = make_float2(__int_as_float(r), dv[r]);
    }
    __syncthreads();

    int c = t & 127;
    int msub = t >> 7;
    int mfirst = msub * 25;
    int O0 = off_s[mfirst] - e0;
    int O1 = off_s[mfirst + 25] - e0;
    const float* h1g = g_h1 + (size_t)g * N_ * 128;
    float* outp = g_h1a + (size_t)n0 * 128 + c;

    int m = mfirst;
    int nb = off_s[m + 1] - e0;
    float acc = 0.f;

    float va[4], wa[4];
#pragma unroll
    for (int i = 0; i < 4; i++) {
        int e = O0 + i;
        if (e < O1) {
            float2 en = (e < CAPA) ? en_s[e]
                      : make_float2(__int_as_float(rowsg[e]), dv[rowsg[e]]);
            wa[i] = en.y;
            va[i] = h1g[(size_t)__float_as_int(en.x) * 128 + c];
        }
    }
#pragma unroll 1
    for (int eb = O0; eb < O1; eb += 4) {
        float vb[4], wb[4];
#pragma unroll
        for (int i = 0; i < 4; i++) {
            int e = eb + 4 + i;
            if (e < O1) {
                float2 en = (e < CAPA) ? en_s[e]
                          : make_float2(__int_as_float(rowsg[e]), dv[rowsg[e]]);
                wb[i] = en.y;
                vb[i] = h1g[(size_t)__float_as_int(en.x) * 128 + c];
            }
        }
#pragma unroll
        for (int i = 0; i < 4; i++) {
            int e = eb + i;
            if (e < O1) {
                while (e == nb) {                 // flush finished node(s)
                    outp[(size_t)m * 128] = acc * dnode[m];
                    acc = 0.f;
                    m++;
                    nb = off_s[m + 1] - e0;
                }
                acc = fmaf(wa[i], va[i], acc);
            }
        }
#pragma unroll
        for (int i = 0; i < 4; i++) { va[i] = vb[i]; wa[i] = wb[i]; }
    }
    // tail flush (last node + any trailing empty nodes)
    for (; m < mfirst + 25; m++) {
        outp[(size_t)m * 128] = acc * dnode[m];
        acc = 0.f;
    }
}

// ---------------- standalone layer-2 GEMM(128->256) + max-pool ----------------
// 50 nodes/block, 256 threads. Stages As[c][m] = h1a + di^2*h1, then channel-quad GEMM.
__global__ __launch_bounds__(256) void k_gemm2pool(
        const float* __restrict__ W_g2, const float* __restrict__ b_g2) {
    __shared__ __align__(16) float As[128*56];  // 28672 B
    __shared__ float dnode[50];
    int n0 = blockIdx.x * 50;
    int g = n0 / N_;
    int lnbase = n0 - g * N_;
    int t = threadIdx.x;

    if (t < 50) dnode[t] = g_dinv[g*N_ + lnbase + t];
    __syncthreads();

    // staging: combine edge aggregate + self term
#pragma unroll
    for (int idx = t; idx < 50*128; idx += 256) {
        int m = idx >> 7;
        int cc = idx & 127;
        float dd = dnode[m] * dnode[m];
        float self = g_h1[(size_t)(n0 + m)*128 + cc];
        float ea   = g_h1a[(size_t)(n0 + m)*128 + cc];
        As[cc*56 + m] = fmaf(dd, self, ea);
    }
    __syncthreads();

    // channel-quad GEMM + fused pool
    {
        int c4 = (t & 63) * 4;
        int mh = t >> 6;
        int mb = mh * 12;
        bool extra = (mh == 3);
        float2 acc[4][7];
#pragma unroll
        for (int j = 0; j < 4; j++)
#pragma unroll
            for (int q = 0; q < 7; q++) acc[j][q] = make_float2(0.f, 0.f);

        const float* Wp = W_g2 + c4;
#pragma unroll 2
        for (int k = 0; k < 128; k++) {
            float4 wv = __ldg((const float4*)(Wp + k*256));
            const float* arow = As + k*56 + mb;
            float4 a0 = *(const float4*)(arow);
            float4 a1 = *(const float4*)(arow + 4);
            float4 a2 = *(const float4*)(arow + 8);
            float wj[4] = {wv.x, wv.y, wv.z, wv.w};
#pragma unroll
            for (int j = 0; j < 4; j++) {
                float2 wp = make_float2(wj[j], wj[j]);
                acc[j][0] = ffma2(make_float2(a0.x, a0.y), wp, acc[j][0]);
                acc[j][1] = ffma2(make_float2(a0.z, a0.w), wp, acc[j][1]);
                acc[j][2] = ffma2(make_float2(a1.x, a1.y), wp, acc[j][2]);
                acc[j][3] = ffma2(make_float2(a1.z, a1.w), wp, acc[j][3]);
                acc[j][4] = ffma2(make_float2(a2.x, a2.y), wp, acc[j][4]);
                acc[j][5] = ffma2(make_float2(a2.z, a2.w), wp, acc[j][5]);
            }
            if (extra) {
                float2 a3 = *(const float2*)(arow + 12);
#pragma unroll
                for (int j = 0; j < 4; j++)
                    acc[j][6] = ffma2(a3, make_float2(wj[j], wj[j]), acc[j][6]);
            }
        }
        float4 bb = __ldg((const float4*)(b_g2 + c4));
        float bj[4] = {bb.x, bb.y, bb.z, bb.w};
#pragma unroll
        for (int j = 0; j < 4; j++) {
            float mx = -1e30f;
#pragma unroll
            for (int q = 0; q < 6; q++) {
                mx = fmaxf(mx, leaky(acc[j][q].x + bj[j]));
                mx = fmaxf(mx, leaky(acc[j][q].y + bj[j]));
            }
            if (extra) {
                mx = fmaxf(mx, leaky(acc[j][6].x + bj[j]));
                mx = fmaxf(mx, leaky(acc[j][6].y + bj[j]));
            }
            atomicMax(&g_pool[g*256 + c4 + j], fkey(mx));
        }
    }
}

// decode pool, FC(256->32, relu) + pe; seeds mu/sigma rows. grid G_, 256 thr.
__global__ void k_fc(const float* __restrict__ W_fc, const float* __restrict__ b_fc,
                     const float* __restrict__ pe, const float* __restrict__ muQ,
                     const float* __restrict__ sigQ) {
    int g = blockIdx.x;
    int t = threadIdx.x;
    __shared__ float ps[256];
    ps[t] = fdec(g_pool[g*256 + t]);
    __syncthreads();
    if (t < 32) {
        float acc = b_fc[t];
        for (int k = 0; k < 256; k++) acc = fmaf(ps[k], W_fc[k*32 + t], acc);
        acc = fmaxf(acc, 0.0f);
        int b = g / 50, s = g - b*50;
        int tk = 2 + s;
        g_xseq[(tk*2 + b)*D_ + t] = acc + pe[tk*D_ + t];
    }
    if (g == 0 && t >= 128 && t < 256) {
        int i = t - 128;
        if (i < 128) {
            int tk = i >> 6;
            int bb = (i >> 5) & 1;
            int d = i & 31;
            g_xseq[(tk*2 + bb)*D_ + d] = (tk == 0 ? muQ[d] : sigQ[d]) + pe[tk*D_ + d];
        }
    }
}

// ---------------- single-kernel transformer (104 resident blocks, grid barrier) ----------------

__device__ __forceinline__ void grid_bar(int target) {
    __syncthreads();
    if (threadIdx.x == 0) {
        __threadfence();
        int v = atomicAdd(&g_bar_cnt, 1);
        if (v + 1 == NB_ * target) {
            g_bar_gen = target;
        } else {
            while (g_bar_gen < target) { }
        }
        __threadfence();
    }
    __syncthreads();
}

__global__ __launch_bounds__(256) void k_transformer(
        const float* __restrict__ in_w, const float* __restrict__ in_b,
        const float* __restrict__ out_w, const float* __restrict__ out_b,
        const float* __restrict__ ln1g, const float* __restrict__ ln1b,
        const float* __restrict__ w1, const float* __restrict__ b1,
        const float* __restrict__ w2, const float* __restrict__ b2,
        const float* __restrict__ ln2g, const float* __restrict__ ln2b,
        float* __restrict__ out) {
    __shared__ float wsq[96*33];
    __shared__ float ow[32*33];
    __shared__ __align__(16) float xv[32];
    __shared__ float at[32];
    __shared__ __align__(16) float xs[32];
    __shared__ float gs[1024];
    __shared__ float ffo[32];
    int tau = blockIdx.x;
    int t = threadIdx.x;
    int wid = t >> 5, lane = t & 31;
    int b = tau & 1;

    if (t < 32) xv[t] = g_xseq[tau*32 + t];

    for (int l = 0; l < 4; l++) {
        for (int idx = t; idx < 96*32; idx += 256)
            wsq[(idx >> 5)*33 + (idx & 31)] = in_w[l*96*32 + idx];
        for (int idx = t; idx < 1024; idx += 256)
            ow[(idx >> 5)*33 + (idx & 31)] = out_w[l*1024 + idx];
        __syncthreads();

        float* qk = g_qkvbuf[l & 1];
        if (t < 96) {
            float acc = in_b[l*96 + t];
#pragma unroll
            for (int d = 0; d < 32; d++) acc = fmaf(xv[d], wsq[t*33 + d], acc);
            qk[tau*96 + t] = acc;
        }
        grid_bar(l + 1);

        if (wid < 4) {
            int h = wid;
            float4 qa = *(const float4*)(qk + tau*96 + h*8);
            float4 qb = *(const float4*)(qk + tau*96 + h*8 + 4);
            int s0 = lane, s1 = lane + 32;
            const float* k0 = qk + (s0*2 + b)*96 + 32 + h*8;
            float4 ka = *(const float4*)(k0);
            float4 kb = *(const float4*)(k0 + 4);
            float sc0 = (qa.x*ka.x + qa.y*ka.y + qa.z*ka.z + qa.w*ka.w +
                         qb.x*kb.x + qb.y*kb.y + qb.z*kb.z + qb.w*kb.w) * 0.35355339059327373f;
            const float* v0p = qk + (s0*2 + b)*96 + 64 + h*8;
            float4 va = *(const float4*)(v0p);
            float4 vb = *(const float4*)(v0p + 4);
            float sc1 = -1e30f;
            float4 wa = make_float4(0.f,0.f,0.f,0.f), wb = wa;
            if (s1 < T_) {
                const float* k1 = qk + (s1*2 + b)*96 + 32 + h*8;
                float4 kc = *(const float4*)(k1);
                float4 kd = *(const float4*)(k1 + 4);
                sc1 = (qa.x*kc.x + qa.y*kc.y + qa.z*kc.z + qa.w*kc.w +
                       qb.x*kd.x + qb.y*kd.y + qb.z*kd.z + qb.w*kd.w) * 0.35355339059327373f;
                const float* v1p = qk + (s1*2 + b)*96 + 64 + h*8;
                wa = *(const float4*)(v1p);
                wb = *(const float4*)(v1p + 4);
            }
            float mx = warp_max(fmaxf(sc0, sc1));
            float p0 = expf(sc0 - mx);
            float p1 = (s1 < T_) ? expf(sc1 - mx) : 0.f;
            float sum = warp_sum(p0 + p1);
            float o[8];
            o[0] = p0*va.x + p1*wa.x;  o[1] = p0*va.y + p1*wa.y;
            o[2] = p0*va.z + p1*wa.z;  o[3] = p0*va.w + p1*wa.w;
            o[4] = p0*vb.x + p1*wb.x;  o[5] = p0*vb.y + p1*wb.y;
            o[6] = p0*vb.z + p1*wb.z;  o[7] = p0*vb.w + p1*wb.w;
#pragma unroll
            for (int e = 0; e < 8; e++) o[e] = warp_sum(o[e]);
            if (lane == 0) {
                float inv = 1.0f / sum;
#pragma unroll
                for (int e = 0; e < 8; e++) at[h*8 + e] = o[e] * inv;
            }
        }
        __syncthreads();

        if (t < 32) {
            float o = out_b[l*32 + t];
#pragma unroll
            for (int c = 0; c < 32; c++) o = fmaf(at[c], ow[t*33 + c], o);
            float val = xv[t] + o;
            float mean = warp_sum(val) * (1.0f/32.0f);
            float dvv = val - mean;
            float var = warp_sum(dvv*dvv) * (1.0f/32.0f);
            xs[t] = dvv * rsqrtf(var + 1e-5f) * ln1g[l*32 + t] + ln1b[l*32 + t];
        }
        __syncthreads();

        float4 xr[8];
#pragma unroll
        for (int i = 0; i < 8; i++) xr[i] = *(const float4*)(xs + i*4);
        const float* w1l = w1 + (size_t)l*1024*32;
        const float* b1l = b1 + l*1024;
#pragma unroll
        for (int i = 0; i < 4; i++) {
            int f = t*4 + i;
            float acc = b1l[f];
            const float4* wr = (const float4*)(w1l + (size_t)f*32);
#pragma unroll
            for (int d4 = 0; d4 < 8; d4++) {
                float4 w = wr[d4];
                float4 x = xr[d4];
                acc = fmaf(w.x, x.x, acc);
                acc = fmaf(w.y, x.y, acc);
                acc = fmaf(w.z, x.z, acc);
                acc = fmaf(w.w, x.w, acc);
            }
            gs[f] = 0.5f * acc * (1.0f + erff(acc * 0.70710678118654752f));
        }
        __syncthreads();
        const float* w2l = w2 + (size_t)l*32*1024;
#pragma unroll
        for (int pass = 0; pass < 4; pass++) {
            int d = pass*8 + wid;
            const float* wrow = w2l + (size_t)d*1024;
            float p = 0.f;
#pragma unroll 8
            for (int j = 0; j < 32; j++) p = fmaf(gs[j*32 + lane], wrow[j*32 + lane], p);
            p = warp_sum(p);
            if (lane == 0) ffo[d] = p;
        }
        __syncthreads();
        if (t < 32) {
            float val = xs[t] + ffo[t] + b2[l*32 + t];
            float mean = warp_sum(val) * (1.0f/32.0f);
            float dvv = val - mean;
            float var = warp_sum(dvv*dvv) * (1.0f/32.0f);
            xv[t] = dvv * rsqrtf(var + 1e-5f) * ln2g[l*32 + t] + ln2b[l*32 + t];
        }
        __syncthreads();
    }

    if (t < 32) {
        float y = xv[t];
        out[128 + tau*32 + t] = y;
        if (tau < 4) out[tau*32 + t] = y;
    }
}

// ---------------- launch ----------------
extern "C" void kernel_launch(void* const* d_in, const int* in_sizes, int n_in,
                              void* d_out, int out_size) {
    const float* v     = (const float*)d_in[0];
    const int*   edge  = (const int*)d_in[2];
    const float* W_emb = (const float*)d_in[3];
    const float* b_emb = (const float*)d_in[4];
    const float* W_g1  = (const float*)d_in[5];
    const float* b_g1  = (const float*)d_in[6];
    const float* W_g2  = (const float*)d_in[7];
    const float* b_g2  = (const float*)d_in[8];
    const float* W_fc  = (const float*)d_in[9];
    const float* b_fc  = (const float*)d_in[10];
    const float* muQ   = (const float*)d_in[11];
    const float* sigQ  = (const float*)d_in[12];
    const float* pe    = (const float*)d_in[13];
    const float* in_w  = (const float*)d_in[14];
    const float* in_b  = (const float*)d_in[15];
    const float* out_w = (const float*)d_in[16];
    const float* out_b = (const float*)d_in[17];
    const float* ln1g  = (const float*)d_in[18];
    const float* ln1b  = (const float*)d_in[19];
    const float* w1    = (const float*)d_in[20];
    const float* b1    = (const float*)d_in[21];
    const float* w2    = (const float*)d_in[22];
    const float* b2    = (const float*)d_in[23];
    const float* ln2g  = (const float*)d_in[24];
    const float* ln2b  = (const float*)d_in[25];

    k_prep<<<G_, 256>>>(edge);                                   // 0
    k_agg_gemm1<<<5000, 128>>>(v, W_emb, b_emb, W_g1, b_g1);     // 1
    k_agg128<<<5000, 256>>>();                                   // 2
    k_gemm2pool<<<5000, 256>>>(W_g2, b_g2);                      // 3 <- ncu capture slot
    k_fc<<<G_, 256>>>(W_fc, b_fc, pe, muQ, sigQ);                // 4
    k_transformer<<<NB_, 256>>>(in_w, in_b, out_w, out_b, ln1g, ln1b,
                                w1, b1, w2, b2, ln2g, ln2b, (float*)d_out);  // 5
}